// round 12
// baseline (speedup 1.0000x reference)
#include <cuda_runtime.h>
#include <cuda_bf16.h>
#include <math.h>
#include <stdint.h>

#define N_TOK 16384
#define D 512
#define SEQL 1024
#define BSZ 16
#define DFF 2048
#define ATT_SCALE 0.125f

typedef __nv_bfloat16 bf16;

// -------------------- fp32 scratch --------------------
__device__ float d_M1[D * D];
__device__ float d_M3[D * D];
__device__ float d_B0[(size_t)N_TOK * D];
__device__ float d_B1[(size_t)N_TOK * D];
__device__ float d_B2[(size_t)N_TOK * D];
__device__ float d_B3[(size_t)N_TOK * D];
__device__ float d_B4[(size_t)N_TOK * D];

// -------------------- split-bf16 weights --------------------
#define OFF_WKG 0
#define OFF_WQG 262144
#define OFF_M1  524288
#define OFF_FCG 786432
#define OFF_M3  1048576
#define OFF_W1  1310720
#define OFF_W2  2359296
#define W_TOTAL 3407872
__device__ bf16 d_Wh[W_TOTAL];
__device__ bf16 d_Wl[W_TOTAL];

// -------------------- split-bf16 activations --------------------
#define ACT_N ((size_t)N_TOK * D)
__device__ bf16 d_XH[ACT_N],   d_XL[ACT_N];
__device__ bf16 d_C1H[ACT_N],  d_C1L[ACT_N];
__device__ bf16 d_QH[ACT_N],   d_QL[ACT_N];
__device__ bf16 d_KH[ACT_N],   d_KL[ACT_N];
__device__ bf16 d_VB[ACT_N];
__device__ bf16 d_ATH[ACT_N],  d_ATL[ACT_N];
__device__ bf16 d_X2CH[ACT_N], d_X2CL[ACT_N];
__device__ bf16 d_X2H[ACT_N],  d_X2L[ACT_N];
__device__ bf16 d_X3H[ACT_N],  d_X3L[ACT_N];
__device__ bf16 d_HIDH[(size_t)N_TOK * DFF], d_HIDL[(size_t)N_TOK * DFF];

// ==================== helpers ====================
__device__ __forceinline__ uint32_t smem_u32(const void* p) {
    uint32_t a;
    asm("{ .reg .u64 t; cvta.to.shared.u64 t, %1; cvt.u32.u64 %0, t; }" : "=r"(a) : "l"(p));
    return a;
}
__device__ __forceinline__ void ldsm4(uint32_t addr, uint32_t& r0, uint32_t& r1, uint32_t& r2, uint32_t& r3) {
    asm volatile("ldmatrix.sync.aligned.m8n8.x4.shared.b16 {%0,%1,%2,%3}, [%4];"
                 : "=r"(r0), "=r"(r1), "=r"(r2), "=r"(r3) : "r"(addr));
}
__device__ __forceinline__ void mma_bf16(float c[4], const uint32_t a[4], uint32_t b0, uint32_t b1) {
    asm volatile(
        "mma.sync.aligned.m16n8k16.row.col.f32.bf16.bf16.f32 "
        "{%0,%1,%2,%3}, {%4,%5,%6,%7}, {%8,%9}, {%0,%1,%2,%3};"
        : "+f"(c[0]), "+f"(c[1]), "+f"(c[2]), "+f"(c[3])
        : "r"(a[0]), "r"(a[1]), "r"(a[2]), "r"(a[3]), "r"(b0), "r"(b1));
}
__device__ __forceinline__ void splitf2(float x, float y, uint32_t& h, uint32_t& l) {
    __nv_bfloat162 hh = __float22bfloat162_rn(make_float2(x, y));
    float2 hf = __bfloat1622float2(hh);
    __nv_bfloat162 ll = __float22bfloat162_rn(make_float2(x - hf.x, y - hf.y));
    h = *(uint32_t*)&hh; l = *(uint32_t*)&ll;
}
__device__ __forceinline__ void split2(float4 v, uint2& hi, uint2& lo) {
    uint32_t h0, l0, h1, l1;
    splitf2(v.x, v.y, h0, l0);
    splitf2(v.z, v.w, h1, l1);
    hi = make_uint2(h0, h1);
    lo = make_uint2(l0, l1);
}
#define CP_ASYNC16(dst, src) asm volatile("cp.async.cg.shared.global [%0], [%1], 16;" :: "r"(dst), "l"(src) : "memory")
#define CP_COMMIT()          asm volatile("cp.async.commit_group;" ::: "memory")
#define CP_WAIT0()           asm volatile("cp.async.wait_group 0;" ::: "memory")
#define CP_WAIT1()           asm volatile("cp.async.wait_group 1;" ::: "memory")

// -------------------- generic fp32 -> bf16 hi/lo split --------------------
__global__ __launch_bounds__(256) void split_w(
    bf16* __restrict__ H, bf16* __restrict__ L, const float* __restrict__ W, int n)
{
    int i = (blockIdx.x * 256 + threadIdx.x) * 4;
    if (i < n) {
        float4 v = *(const float4*)(W + i);
        uint2 h, l; split2(v, h, l);
        *(uint2*)(H + i) = h;
        *(uint2*)(L + i) = l;
    }
}

// ==================== 16-warp 2-stage split-bf16 mma GEMM ====================
// 512 threads, warp tile 16x64, CTA tile 128x128, BK=64, 2-stage cp.async.
#define T_AH 0
#define T_AL 18432
#define T_BH 36864
#define T_BL 55296
#define STG  73728
#define TCG_SMEM (2 * STG)

__global__ __launch_bounds__(512, 1) void mma_gemm(
    float* __restrict__ C, bf16* __restrict__ Ch, bf16* __restrict__ Cl,
    const bf16* __restrict__ Ah, const bf16* __restrict__ Al,
    const bf16* __restrict__ Bh, const bf16* __restrict__ Bl,
    int M, int Nt, int K, const float* __restrict__ bias, int act)
{
    extern __shared__ char smem[];
    const uint32_t sb = smem_u32(smem);
    const int tid = threadIdx.x, wid = tid >> 5, lane = tid & 31;
    const int m0 = blockIdx.y * 128, n0 = blockIdx.x * 128;
    const int wm = (wid & 7) << 4;     // warp M offset: 0..112
    const int wn = (wid >> 3) << 6;    // warp N offset: 0 or 64
    const int quad = lane >> 3, r = lane & 7;
    const int arow = ((quad & 1) << 3) + r, ak = (quad >> 1) << 3;
    const int brow = ((quad >> 1) << 3) + r, bk = (quad & 1) << 3;
    const int ldr = tid >> 3, ldc = tid & 7;   // cp.async: row (0..63 per half), chunk

    float acc[8][4];
    #pragma unroll
    for (int j = 0; j < 8; j++)
        #pragma unroll
        for (int q = 0; q < 4; q++) acc[j][q] = 0.f;

    const int nit = K >> 6;

    // prologue: fill stage 0
    #pragma unroll
    for (int j = 0; j < 2; j++) {
        int row = ldr + (j << 6);
        uint32_t so = row * 144 + ldc * 16;
        size_t ga = (size_t)(m0 + row) * K + ldc * 8;
        size_t gb = (size_t)(n0 + row) * K + ldc * 8;
        CP_ASYNC16(sb + T_AH + so, Ah + ga);
        CP_ASYNC16(sb + T_AL + so, Al + ga);
        CP_ASYNC16(sb + T_BH + so, Bh + gb);
        CP_ASYNC16(sb + T_BL + so, Bl + gb);
    }
    CP_COMMIT();

    for (int it = 0; it < nit; it++) {
        const uint32_t cs = sb + (it & 1) * STG;
        if (it + 1 < nit) {
            const uint32_t ns = sb + ((it + 1) & 1) * STG;
            const int k0 = (it + 1) << 6;
            #pragma unroll
            for (int j = 0; j < 2; j++) {
                int row = ldr + (j << 6);
                uint32_t so = row * 144 + ldc * 16;
                size_t ga = (size_t)(m0 + row) * K + k0 + ldc * 8;
                size_t gb = (size_t)(n0 + row) * K + k0 + ldc * 8;
                CP_ASYNC16(ns + T_AH + so, Ah + ga);
                CP_ASYNC16(ns + T_AL + so, Al + ga);
                CP_ASYNC16(ns + T_BH + so, Bh + gb);
                CP_ASYNC16(ns + T_BL + so, Bl + gb);
            }
            CP_COMMIT();
            CP_WAIT1();
        } else {
            CP_WAIT0();
        }
        __syncthreads();
        #pragma unroll
        for (int kc = 0; kc < 4; kc++) {
            uint32_t ah[4], al[4];
            uint32_t ao = cs + (wm + arow) * 144 + ((kc << 4) + ak) * 2;
            ldsm4(ao + T_AH, ah[0], ah[1], ah[2], ah[3]);
            ldsm4(ao + T_AL, al[0], al[1], al[2], al[3]);
            #pragma unroll
            for (int jj = 0; jj < 4; jj++) {
                uint32_t bo = cs + (wn + (jj << 4) + brow) * 144 + ((kc << 4) + bk) * 2;
                uint32_t bh0, bh1, bh2, bh3, bl0, bl1, bl2, bl3;
                ldsm4(bo + T_BH, bh0, bh1, bh2, bh3);
                ldsm4(bo + T_BL, bl0, bl1, bl2, bl3);
                mma_bf16(acc[2 * jj],     ah, bh0, bh1);
                mma_bf16(acc[2 * jj],     ah, bl0, bl1);
                mma_bf16(acc[2 * jj],     al, bh0, bh1);
                mma_bf16(acc[2 * jj + 1], ah, bh2, bh3);
                mma_bf16(acc[2 * jj + 1], ah, bl2, bl3);
                mma_bf16(acc[2 * jj + 1], al, bh2, bh3);
            }
        }
        __syncthreads();
    }

    const int g = lane >> 2, tg = (lane & 3) << 1;
    const int row0 = m0 + wm + g;
    #pragma unroll
    for (int j = 0; j < 8; j++) {
        const int col = n0 + wn + (j << 3) + tg;
        float b0 = 0.f, b1 = 0.f;
        if (bias) { b0 = bias[col]; b1 = bias[col + 1]; }
        float v0 = acc[j][0] + b0, v1 = acc[j][1] + b1;
        float v2 = acc[j][2] + b0, v3 = acc[j][3] + b1;
        if (act) {
            v0 = 0.5f * v0 * (1.0f + erff(v0 * 0.70710678118654752f));
            v1 = 0.5f * v1 * (1.0f + erff(v1 * 0.70710678118654752f));
            v2 = 0.5f * v2 * (1.0f + erff(v2 * 0.70710678118654752f));
            v3 = 0.5f * v3 * (1.0f + erff(v3 * 0.70710678118654752f));
        }
        if (C) {
            *(float2*)(C + (size_t)row0 * Nt + col) = make_float2(v0, v1);
            *(float2*)(C + (size_t)(row0 + 8) * Nt + col) = make_float2(v2, v3);
        }
        if (Ch) {
            uint32_t h0, l0, h1, l1;
            splitf2(v0, v1, h0, l0);
            splitf2(v2, v3, h1, l1);
            *(uint32_t*)(Ch + (size_t)row0 * Nt + col) = h0;
            *(uint32_t*)(Ch + (size_t)(row0 + 8) * Nt + col) = h1;
            if (Cl) {
                *(uint32_t*)(Cl + (size_t)row0 * Nt + col) = l0;
                *(uint32_t*)(Cl + (size_t)(row0 + 8) * Nt + col) = l1;
            }
        }
    }
}

// -------------------- GEMM NN (fp32, tiny: weight folding) --------------------
__global__ __launch_bounds__(256) void gemm_nn(
    float* __restrict__ C, const float* __restrict__ A, const float* __restrict__ B,
    int M, int N, int K)
{
    __shared__ float As[16][64];
    __shared__ float Bs[16][64];
    const int tid = threadIdx.x;
    const int tx = tid & 15, ty = tid >> 4;
    const int lr = tid >> 2, lc = (tid & 3) << 2;
    const int bkr = tid >> 4, bnc = (tid & 15) << 2;
    const float* Ab = A + (size_t)blockIdx.y * 64 * K;
    float acc[4][4] = {};
    for (int k0 = 0; k0 < K; k0 += 16) {
        float4 a4 = *(const float4*)(Ab + (size_t)lr * K + k0 + lc);
        float4 b4 = *(const float4*)(B + (size_t)(k0 + bkr) * N + blockIdx.x * 64 + bnc);
        __syncthreads();
        As[lc + 0][lr] = a4.x; As[lc + 1][lr] = a4.y; As[lc + 2][lr] = a4.z; As[lc + 3][lr] = a4.w;
        *(float4*)&Bs[bkr][bnc] = b4;
        __syncthreads();
        #pragma unroll
        for (int k = 0; k < 16; k++) {
            float4 av = *(const float4*)&As[k][ty << 2];
            float4 bv = *(const float4*)&Bs[k][tx << 2];
            float a[4] = {av.x, av.y, av.z, av.w};
            float b[4] = {bv.x, bv.y, bv.z, bv.w};
            #pragma unroll
            for (int i = 0; i < 4; i++)
                #pragma unroll
                for (int j = 0; j < 4; j++) acc[i][j] += a[i] * b[j];
        }
    }
    #pragma unroll
    for (int i = 0; i < 4; i++) {
        int m = blockIdx.y * 64 + (ty << 2) + i;
        #pragma unroll
        for (int j = 0; j < 4; j++)
            C[(size_t)m * N + blockIdx.x * 64 + (tx << 2) + j] = acc[i][j];
    }
}

// ==================== tensor-core flash attention ====================
#define AQ_H 0
#define AQ_L 18432
#define AK_B(s) (36864 + (s) * 18432)
#define AVT  73728
#define AT_SMEM 82944

__global__ __launch_bounds__(256, 1) void attn_mma(
    bf16* __restrict__ Oh, bf16* __restrict__ Ol,
    const bf16* __restrict__ Qh, const bf16* __restrict__ Ql,
    const bf16* __restrict__ Kh, const bf16* __restrict__ Kl,
    const bf16* __restrict__ Vb)
{
    extern __shared__ char smem[];
    const uint32_t sb = smem_u32(smem);
    const int tid = threadIdx.x, wid = tid >> 5, lane = tid & 31;
    const int b = blockIdx.z, h = blockIdx.y;
    const int q0 = blockIdx.x * 128;
    const size_t tok0 = (size_t)b * SEQL;
    const int hc = h * 64;
    const int quad = lane >> 3, r = lane & 7;
    const int arow = ((quad & 1) << 3) + r, ak = (quad >> 1) << 3;
    const int brow = ((quad >> 1) << 3) + r, bk = (quad & 1) << 3;
    const int g = lane >> 2, tg = lane & 3;
    const int wq0 = wid << 4;

    {
        #pragma unroll
        for (int j = 0; j < 4; j++) {
            int ch = tid + (j << 8);
            int row = ch >> 3, cc = ch & 7;
            uint32_t so = row * 144 + cc * 16;
            size_t ga = (tok0 + q0 + row) * D + hc + cc * 8;
            CP_ASYNC16(sb + AQ_H + so, Qh + ga);
            CP_ASYNC16(sb + AQ_L + so, Ql + ga);
        }
        #pragma unroll
        for (int j = 0; j < 2; j++) {
            int ch = tid + (j << 8);
            int row = ch >> 3, cc = ch & 7;
            uint32_t so = row * 144 + cc * 16;
            size_t ga = (tok0 + row) * D + hc + cc * 8;
            CP_ASYNC16(sb + AK_B(0) + so, Kh + ga);
            CP_ASYNC16(sb + AK_B(0) + 9216 + so, Kl + ga);
        }
        CP_COMMIT();
    }
    uint4 vr[2];
    #pragma unroll
    for (int j = 0; j < 2; j++) {
        int ch = tid + (j << 8);
        int row = ch >> 3, cc = ch & 7;
        vr[j] = *(const uint4*)(Vb + (tok0 + row) * D + hc + cc * 8);
    }

    float o[8][4];
    #pragma unroll
    for (int j = 0; j < 8; j++)
        #pragma unroll
        for (int q = 0; q < 4; q++) o[j][q] = 0.f;
    float m0r = -1e30f, m1r = -1e30f, l0r = 0.f, l1r = 0.f;

    for (int kt = 0; kt < SEQL / 64; kt++) {
        const int s = kt & 1;
        if (kt + 1 < SEQL / 64) {
            const size_t kb = tok0 + (size_t)(kt + 1) * 64;
            #pragma unroll
            for (int j = 0; j < 2; j++) {
                int ch = tid + (j << 8);
                int row = ch >> 3, cc = ch & 7;
                uint32_t so = row * 144 + cc * 16;
                size_t ga = (kb + row) * D + hc + cc * 8;
                CP_ASYNC16(sb + AK_B(1 - s) + so, Kh + ga);
                CP_ASYNC16(sb + AK_B(1 - s) + 9216 + so, Kl + ga);
            }
            CP_COMMIT();
        }
        #pragma unroll
        for (int j = 0; j < 2; j++) {
            int ch = tid + (j << 8);
            int row = ch >> 3, cc = ch & 7;
            const bf16* pv = (const bf16*)&vr[j];
            #pragma unroll
            for (int e = 0; e < 8; e++) {
                int d = cc * 8 + e;
                *(bf16*)(smem + AVT + d * 144 + row * 2) = pv[e];
            }
        }
        if (kt + 1 < SEQL / 64) { CP_WAIT1(); } else { CP_WAIT0(); }
        __syncthreads();
        if (kt + 1 < SEQL / 64) {
            const size_t kb = tok0 + (size_t)(kt + 1) * 64;
            #pragma unroll
            for (int j = 0; j < 2; j++) {
                int ch = tid + (j << 8);
                int row = ch >> 3, cc = ch & 7;
                vr[j] = *(const uint4*)(Vb + (kb + row) * D + hc + cc * 8);
            }
        }
        float sc[8][4];
        #pragma unroll
        for (int j = 0; j < 8; j++)
            #pragma unroll
            for (int q = 0; q < 4; q++) sc[j][q] = 0.f;
        #pragma unroll
        for (int kc = 0; kc < 4; kc++) {
            uint32_t ah[4], al[4];
            uint32_t ao = sb + (wq0 + arow) * 144 + ((kc << 4) + ak) * 2;
            ldsm4(ao + AQ_H, ah[0], ah[1], ah[2], ah[3]);
            ldsm4(ao + AQ_L, al[0], al[1], al[2], al[3]);
            #pragma unroll
            for (int jj = 0; jj < 4; jj++) {
                uint32_t bo = sb + AK_B(s) + ((jj << 4) + brow) * 144 + ((kc << 4) + bk) * 2;
                uint32_t bh0, bh1, bh2, bh3, bl0, bl1, bl2, bl3;
                ldsm4(bo, bh0, bh1, bh2, bh3);
                ldsm4(bo + 9216, bl0, bl1, bl2, bl3);
                mma_bf16(sc[2 * jj],     ah, bh0, bh1);
                mma_bf16(sc[2 * jj],     ah, bl0, bl1);
                mma_bf16(sc[2 * jj],     al, bh0, bh1);
                mma_bf16(sc[2 * jj + 1], ah, bh2, bh3);
                mma_bf16(sc[2 * jj + 1], ah, bl2, bl3);
                mma_bf16(sc[2 * jj + 1], al, bh2, bh3);
            }
        }
        float mx0 = -1e30f, mx1 = -1e30f;
        #pragma unroll
        for (int j = 0; j < 8; j++) {
            sc[j][0] *= ATT_SCALE; sc[j][1] *= ATT_SCALE;
            sc[j][2] *= ATT_SCALE; sc[j][3] *= ATT_SCALE;
            mx0 = fmaxf(mx0, fmaxf(sc[j][0], sc[j][1]));
            mx1 = fmaxf(mx1, fmaxf(sc[j][2], sc[j][3]));
        }
        mx0 = fmaxf(mx0, __shfl_xor_sync(0xffffffffu, mx0, 1));
        mx0 = fmaxf(mx0, __shfl_xor_sync(0xffffffffu, mx0, 2));
        mx1 = fmaxf(mx1, __shfl_xor_sync(0xffffffffu, mx1, 1));
        mx1 = fmaxf(mx1, __shfl_xor_sync(0xffffffffu, mx1, 2));
        float mn0 = fmaxf(m0r, mx0), mn1 = fmaxf(m1r, mx1);
        float a0 = __expf(m0r - mn0), a1 = __expf(m1r - mn1);
        m0r = mn0; m1r = mn1;
        float rs0 = 0.f, rs1 = 0.f;
        #pragma unroll
        for (int j = 0; j < 8; j++) {
            sc[j][0] = __expf(sc[j][0] - mn0); sc[j][1] = __expf(sc[j][1] - mn0);
            sc[j][2] = __expf(sc[j][2] - mn1); sc[j][3] = __expf(sc[j][3] - mn1);
            rs0 += sc[j][0] + sc[j][1];
            rs1 += sc[j][2] + sc[j][3];
        }
        rs0 += __shfl_xor_sync(0xffffffffu, rs0, 1);
        rs0 += __shfl_xor_sync(0xffffffffu, rs0, 2);
        rs1 += __shfl_xor_sync(0xffffffffu, rs1, 1);
        rs1 += __shfl_xor_sync(0xffffffffu, rs1, 2);
        l0r = l0r * a0 + rs0;
        l1r = l1r * a1 + rs1;
        #pragma unroll
        for (int j = 0; j < 8; j++) {
            o[j][0] *= a0; o[j][1] *= a0; o[j][2] *= a1; o[j][3] *= a1;
        }
        #pragma unroll
        for (int kk = 0; kk < 4; kk++) {
            uint32_t pa[4];
            __nv_bfloat162 t0 = __float22bfloat162_rn(make_float2(sc[2 * kk][0], sc[2 * kk][1]));
            __nv_bfloat162 t1 = __float22bfloat162_rn(make_float2(sc[2 * kk][2], sc[2 * kk][3]));
            __nv_bfloat162 t2 = __float22bfloat162_rn(make_float2(sc[2 * kk + 1][0], sc[2 * kk + 1][1]));
            __nv_bfloat162 t3 = __float22bfloat162_rn(make_float2(sc[2 * kk + 1][2], sc[2 * kk + 1][3]));
            pa[0] = *(uint32_t*)&t0; pa[1] = *(uint32_t*)&t1;
            pa[2] = *(uint32_t*)&t2; pa[3] = *(uint32_t*)&t3;
            #pragma unroll
            for (int jj = 0; jj < 4; jj++) {
                uint32_t bo = sb + AVT + ((jj << 4) + brow) * 144 + ((kk << 4) + bk) * 2;
                uint32_t b0, b1, b2, b3;
                ldsm4(bo, b0, b1, b2, b3);
                mma_bf16(o[2 * jj],     pa, b0, b1);
                mma_bf16(o[2 * jj + 1], pa, b2, b3);
            }
        }
        __syncthreads();
    }
    const float inv0 = 1.0f / l0r, inv1 = 1.0f / l1r;
    #pragma unroll
    for (int j = 0; j < 8; j++) {
        int col = hc + (j << 3) + (tg << 1);
        size_t r0 = (tok0 + q0 + wq0 + g) * D + col;
        size_t r1 = (tok0 + q0 + wq0 + g + 8) * D + col;
        uint32_t h0, l0, h1, l1;
        splitf2(o[j][0] * inv0, o[j][1] * inv0, h0, l0);
        splitf2(o[j][2] * inv1, o[j][3] * inv1, h1, l1);
        *(uint32_t*)(Oh + r0) = h0; *(uint32_t*)(Ol + r0) = l0;
        *(uint32_t*)(Oh + r1) = h1; *(uint32_t*)(Ol + r1) = l1;
    }
}

// -------------------- conv along feature dim -> split bf16 out --------------------
__global__ __launch_bounds__(128) void conv_row(
    bf16* __restrict__ outH, bf16* __restrict__ outL,
    const float* __restrict__ in, const float* __restrict__ w)
{
    __shared__ float rb[D];
    const int row = blockIdx.x, t = threadIdx.x;
    float4 v = *(const float4*)(in + (size_t)row * D + t * 4);
    *(float4*)&rb[t * 4] = v;
    __syncthreads();
    const float w0 = w[0], w1 = w[1], w2 = w[2];
    float y[4];
    #pragma unroll
    for (int i = 0; i < 4; i++) {
        int c = t * 4 + i;
        float xm = (c > 0) ? rb[c - 1] : 0.f;
        float xp = (c < D - 1) ? rb[c + 1] : 0.f;
        y[i] = w0 * xm + w1 * rb[c] + w2 * xp;
    }
    uint32_t h0, l0, h1, l1;
    splitf2(y[0], y[1], h0, l0);
    splitf2(y[2], y[3], h1, l1);
    *(uint2*)(outH + (size_t)row * D + t * 4) = make_uint2(h0, h1);
    *(uint2*)(outL + (size_t)row * D + t * 4) = make_uint2(l0, l1);
}

// -------------------- LN(a+b)*g+be --------------------
__global__ __launch_bounds__(128) void ln_kernel(
    float* __restrict__ out, bf16* __restrict__ outH, bf16* __restrict__ outL,
    const float* __restrict__ a, const float* __restrict__ b,
    const float* __restrict__ g, const float* __restrict__ be,
    float* __restrict__ hn_out, int do_hn)
{
    __shared__ float sh[8];
    const int row = blockIdx.x, t = threadIdx.x;
    float4 av = *(const float4*)(a + (size_t)row * D + t * 4);
    float4 bv = *(const float4*)(b + (size_t)row * D + t * 4);
    float v[4] = {av.x + bv.x, av.y + bv.y, av.z + bv.z, av.w + bv.w};
    float s = v[0] + v[1] + v[2] + v[3];
    float s2 = v[0] * v[0] + v[1] * v[1] + v[2] * v[2] + v[3] * v[3];
    #pragma unroll
    for (int off = 16; off; off >>= 1) {
        s += __shfl_xor_sync(0xffffffffu, s, off);
        s2 += __shfl_xor_sync(0xffffffffu, s2, off);
    }
    if ((t & 31) == 0) { sh[t >> 5] = s; sh[4 + (t >> 5)] = s2; }
    __syncthreads();
    s = sh[0] + sh[1] + sh[2] + sh[3];
    s2 = sh[4] + sh[5] + sh[6] + sh[7];
    const float mean = s * (1.0f / D);
    const float rstd = rsqrtf(s2 * (1.0f / D) - mean * mean + 1e-5f);
    float4 gv = *(const float4*)(g + t * 4);
    float4 bev = *(const float4*)(be + t * 4);
    float y[4];
    y[0] = (v[0] - mean) * rstd * gv.x + bev.x;
    y[1] = (v[1] - mean) * rstd * gv.y + bev.y;
    y[2] = (v[2] - mean) * rstd * gv.z + bev.z;
    y[3] = (v[3] - mean) * rstd * gv.w + bev.w;
    *(float4*)(out + (size_t)row * D + t * 4) = make_float4(y[0], y[1], y[2], y[3]);
    if (outH) {
        uint32_t h0, l0, h1, l1;
        splitf2(y[0], y[1], h0, l0);
        splitf2(y[2], y[3], h1, l1);
        *(uint2*)(outH + (size_t)row * D + t * 4) = make_uint2(h0, h1);
        *(uint2*)(outL + (size_t)row * D + t * 4) = make_uint2(l0, l1);
    }
    if (do_hn && (row & (SEQL - 1)) == SEQL - 1)
        *(float4*)(hn_out + (size_t)(row >> 10) * D + t * 4) = av;
}

// -------------------- fused LN1 + conv2 --------------------
__global__ __launch_bounds__(128) void ln_conv_kernel(
    float* __restrict__ x1, bf16* __restrict__ x2cH, bf16* __restrict__ x2cL,
    const float* __restrict__ a, const float* __restrict__ b,
    const float* __restrict__ g, const float* __restrict__ be,
    const float* __restrict__ w)
{
    __shared__ float sh[8];
    __shared__ float rb[D];
    const int row = blockIdx.x, t = threadIdx.x;
    float4 av = *(const float4*)(a + (size_t)row * D + t * 4);
    float4 bv = *(const float4*)(b + (size_t)row * D + t * 4);
    float v[4] = {av.x + bv.x, av.y + bv.y, av.z + bv.z, av.w + bv.w};
    float s = v[0] + v[1] + v[2] + v[3];
    float s2 = v[0] * v[0] + v[1] * v[1] + v[2] * v[2] + v[3] * v[3];
    #pragma unroll
    for (int off = 16; off; off >>= 1) {
        s += __shfl_xor_sync(0xffffffffu, s, off);
        s2 += __shfl_xor_sync(0xffffffffu, s2, off);
    }
    if ((t & 31) == 0) { sh[t >> 5] = s; sh[4 + (t >> 5)] = s2; }
    __syncthreads();
    s = sh[0] + sh[1] + sh[2] + sh[3];
    s2 = sh[4] + sh[5] + sh[6] + sh[7];
    const float mean = s * (1.0f / D);
    const float rstd = rsqrtf(s2 * (1.0f / D) - mean * mean + 1e-5f);
    float4 gv = *(const float4*)(g + t * 4);
    float4 bev = *(const float4*)(be + t * 4);
    float y[4];
    y[0] = (v[0] - mean) * rstd * gv.x + bev.x;
    y[1] = (v[1] - mean) * rstd * gv.y + bev.y;
    y[2] = (v[2] - mean) * rstd * gv.z + bev.z;
    y[3] = (v[3] - mean) * rstd * gv.w + bev.w;
    *(float4*)&rb[t * 4] = make_float4(y[0], y[1], y[2], y[3]);
    *(float4*)(x1 + (size_t)row * D + t * 4) = make_float4(y[0], y[1], y[2], y[3]);
    __syncthreads();
    const float w0 = w[0], w1 = w[1], w2 = w[2];
    float z[4];
    #pragma unroll
    for (int i = 0; i < 4; i++) {
        int c = t * 4 + i;
        float xm = (c > 0) ? rb[c - 1] : 0.f;
        float xp = (c < D - 1) ? rb[c + 1] : 0.f;
        z[i] = w0 * xm + w1 * rb[c] + w2 * xp;
    }
    uint32_t h0, l0, h1, l1;
    splitf2(z[0], z[1], h0, l0);
    splitf2(z[2], z[3], h1, l1);
    *(uint2*)(x2cH + (size_t)row * D + t * 4) = make_uint2(h0, h1);
    *(uint2*)(x2cL + (size_t)row * D + t * 4) = make_uint2(l0, l1);
}

// -------------------- launch --------------------
extern "C" void kernel_launch(void* const* d_in, const int* in_sizes, int n_in,
                              void* d_out, int out_size)
{
    const float* input   = (const float*)d_in[0];
    const float* wq_c    = (const float*)d_in[3];
    const float* fc_c    = (const float*)d_in[5];
    const float* wq_g    = (const float*)d_in[6];
    const float* wk_g    = (const float*)d_in[7];
    const float* fc_g    = (const float*)d_in[8];
    const float* wq_x    = (const float*)d_in[9];
    const float* fc_x    = (const float*)d_in[11];
    const float* conv1_w = (const float*)d_in[12];
    const float* conv2_w = (const float*)d_in[13];
    const float* ln1_g = (const float*)d_in[14];
    const float* ln1_b = (const float*)d_in[15];
    const float* ln2_g = (const float*)d_in[16];
    const float* ln2_b = (const float*)d_in[17];
    const float* ln3_g = (const float*)d_in[18];
    const float* ln3_b = (const float*)d_in[19];
    const float* ln4_g = (const float*)d_in[20];
    const float* ln4_b = (const float*)d_in[21];
    const float* mlp_w1 = (const float*)d_in[22];
    const float* mlp_b1 = (const float*)d_in[23];
    const float* mlp_w2 = (const float*)d_in[24];
    const float* mlp_b2 = (const float*)d_in[25];

    float *M1, *M3, *B0, *B1, *B2, *B3, *B4;
    bf16 *Wh, *Wl, *XH, *XL, *C1H, *C1L, *QH, *QL, *KH, *KL, *VB;
    bf16 *ATH, *ATL, *X2CH, *X2CL, *X2H, *X2L, *X3H, *X3L, *HIDH, *HIDL;
    cudaGetSymbolAddress((void**)&M1, d_M1);
    cudaGetSymbolAddress((void**)&M3, d_M3);
    cudaGetSymbolAddress((void**)&B0, d_B0);
    cudaGetSymbolAddress((void**)&B1, d_B1);
    cudaGetSymbolAddress((void**)&B2, d_B2);
    cudaGetSymbolAddress((void**)&B3, d_B3);
    cudaGetSymbolAddress((void**)&B4, d_B4);
    cudaGetSymbolAddress((void**)&Wh, d_Wh);
    cudaGetSymbolAddress((void**)&Wl, d_Wl);
    cudaGetSymbolAddress((void**)&XH, d_XH);
    cudaGetSymbolAddress((void**)&XL, d_XL);
    cudaGetSymbolAddress((void**)&C1H, d_C1H);
    cudaGetSymbolAddress((void**)&C1L, d_C1L);
    cudaGetSymbolAddress((void**)&QH, d_QH);
    cudaGetSymbolAddress((void**)&QL, d_QL);
    cudaGetSymbolAddress((void**)&KH, d_KH);
    cudaGetSymbolAddress((void**)&KL, d_KL);
    cudaGetSymbolAddress((void**)&VB, d_VB);
    cudaGetSymbolAddress((void**)&ATH, d_ATH);
    cudaGetSymbolAddress((void**)&ATL, d_ATL);
    cudaGetSymbolAddress((void**)&X2CH, d_X2CH);
    cudaGetSymbolAddress((void**)&X2CL, d_X2CL);
    cudaGetSymbolAddress((void**)&X2H, d_X2H);
    cudaGetSymbolAddress((void**)&X2L, d_X2L);
    cudaGetSymbolAddress((void**)&X3H, d_X3H);
    cudaGetSymbolAddress((void**)&X3L, d_X3L);
    cudaGetSymbolAddress((void**)&HIDH, d_HIDH);
    cudaGetSymbolAddress((void**)&HIDL, d_HIDL);

    cudaFuncSetAttribute(mma_gemm, cudaFuncAttributeMaxDynamicSharedMemorySize, TCG_SMEM);
    cudaFuncSetAttribute(attn_mma, cudaFuncAttributeMaxDynamicSharedMemorySize, AT_SMEM);

    float* outp = (float*)d_out;
    const size_t out_main = (size_t)N_TOK * D;
    float* hnp = outp + out_main;
    int do_hn = (out_size >= (int)(out_main + BSZ * D)) ? 1 : 0;
    if (!do_hn) hnp = outp;

    const dim3 blk(256);
    const dim3 gblk(512);
    const dim3 tg512(D / 128, N_TOK / 128);
    const dim3 tg2048(DFF / 128, N_TOK / 128);
    const dim3 gW(D / 64, D / 64);
    const int nW512 = D * D / 1024;
    const int nW2048 = D * DFF / 1024;
    const int nX = N_TOK * D / 1024;

    // launches 0-4 (prep needed before first GEMM); launch 5 = mma_gemm (ncu target)
    gemm_nn<<<gW, blk>>>(M1, fc_c, wq_c, D, D, D);
    gemm_nn<<<gW, blk>>>(M3, fc_x, wq_x, D, D, D);
    split_w<<<nW512, blk>>>(Wh + OFF_WKG, Wl + OFF_WKG, wk_g, D * D);
    split_w<<<nW512, blk>>>(Wh + OFF_WQG, Wl + OFF_WQG, wq_g, D * D);
    split_w<<<nX, blk>>>(XH, XL, input, N_TOK * D);

    mma_gemm<<<tg512, gblk, TCG_SMEM>>>(nullptr, KH, KL, XH, XL, Wh + OFF_WKG, Wl + OFF_WKG, N_TOK, D, D, nullptr, 0);
    mma_gemm<<<tg512, gblk, TCG_SMEM>>>(nullptr, VB, nullptr, XH, XL, Wh + OFF_WQG, Wl + OFF_WQG, N_TOK, D, D, nullptr, 0);

    conv_row<<<N_TOK, 128>>>(C1H, C1L, input, conv1_w);
    split_w<<<nW512, blk>>>(Wh + OFF_M1, Wl + OFF_M1, M1, D * D);
    mma_gemm<<<tg512, gblk, TCG_SMEM>>>(B1, nullptr, nullptr, C1H, C1L, Wh + OFF_M1, Wl + OFF_M1, N_TOK, D, D, nullptr, 0);
    ln_conv_kernel<<<N_TOK, 128>>>(B2, X2CH, X2CL, B1, input, ln1_g, ln1_b, conv2_w);

    mma_gemm<<<tg512, gblk, TCG_SMEM>>>(nullptr, QH, QL, X2CH, X2CL, Wh + OFF_WQG, Wl + OFF_WQG, N_TOK, D, D, nullptr, 0);
    attn_mma<<<dim3(SEQL / 128, 8, BSZ), blk, AT_SMEM>>>(ATH, ATL, QH, QL, KH, KL, VB);
    split_w<<<nW512, blk>>>(Wh + OFF_FCG, Wl + OFF_FCG, fc_g, D * D);
    mma_gemm<<<tg512, gblk, TCG_SMEM>>>(B0, nullptr, nullptr, ATH, ATL, Wh + OFF_FCG, Wl + OFF_FCG, N_TOK, D, D, nullptr, 0);
    ln_kernel<<<N_TOK, 128>>>(B3, X2H, X2L, B0, B2, ln2_g, ln2_b, hnp, 0);

    split_w<<<nW512, blk>>>(Wh + OFF_M3, Wl + OFF_M3, M3, D * D);
    mma_gemm<<<tg512, gblk, TCG_SMEM>>>(B1, nullptr, nullptr, X2H, X2L, Wh + OFF_M3, Wl + OFF_M3, N_TOK, D, D, nullptr, 0);
    ln_kernel<<<N_TOK, 128>>>(B4, X3H, X3L, B1, B3, ln3_g, ln3_b, hnp, do_hn);

    split_w<<<nW2048, blk>>>(Wh + OFF_W1, Wl + OFF_W1, mlp_w1, D * DFF);
    split_w<<<nW2048, blk>>>(Wh + OFF_W2, Wl + OFF_W2, mlp_w2, D * DFF);
    mma_gemm<<<tg2048, gblk, TCG_SMEM>>>(nullptr, HIDH, HIDL, X3H, X3L, Wh + OFF_W1, Wl + OFF_W1, N_TOK, DFF, D, mlp_b1, 1);
    mma_gemm<<<tg512, gblk, TCG_SMEM>>>(B0, nullptr, nullptr, HIDH, HIDL, Wh + OFF_W2, Wl + OFF_W2, N_TOK, D, DFF, mlp_b2, 0);
    ln_kernel<<<N_TOK, 128>>>(outp, nullptr, nullptr, B0, B4, ln4_g, ln4_b, hnp, 0);
}

// round 13
// speedup vs baseline: 1.0764x; 1.0764x over previous
#include <cuda_runtime.h>
#include <cuda_bf16.h>
#include <math.h>
#include <stdint.h>

#define N_TOK 16384
#define D 512
#define SEQL 1024
#define BSZ 16
#define DFF 2048
#define KVD 1024
#define ATT_SCALE 0.125f

typedef __nv_bfloat16 bf16;

// -------------------- fp32 scratch --------------------
__device__ float d_M1[D * D];
__device__ float d_M3[D * D];
__device__ float d_B0[(size_t)N_TOK * D];
__device__ float d_B1[(size_t)N_TOK * D];
__device__ float d_B2[(size_t)N_TOK * D];
__device__ float d_B3[(size_t)N_TOK * D];
__device__ float d_B4[(size_t)N_TOK * D];

// -------------------- split-bf16 weights --------------------
#define OFF_WKG  0
#define OFF_WQG  262144
#define OFF_M1   524288
#define OFF_FCG  786432
#define OFF_M3   1048576
#define OFF_W1   1310720
#define OFF_W2   2359296
#define OFF_WQG2 3407872
#define W_TOTAL  3670016
__device__ bf16 d_Wh[W_TOTAL];
__device__ bf16 d_Wl[W_TOTAL];

// -------------------- split-bf16 activations --------------------
#define ACT_N ((size_t)N_TOK * D)
__device__ bf16 d_XH[ACT_N],   d_XL[ACT_N];
__device__ bf16 d_KVH[(size_t)N_TOK * KVD], d_KVL[(size_t)N_TOK * KVD];
__device__ bf16 d_QH[ACT_N],   d_QL[ACT_N];
__device__ bf16 d_ATH[ACT_N],  d_ATL[ACT_N];
__device__ bf16 d_X1H[ACT_N],  d_X1L[ACT_N];
__device__ bf16 d_X2H[ACT_N],  d_X2L[ACT_N];
__device__ bf16 d_X3H[ACT_N],  d_X3L[ACT_N];
__device__ bf16 d_HIDH[(size_t)N_TOK * DFF], d_HIDL[(size_t)N_TOK * DFF];

// ==================== helpers ====================
__device__ __forceinline__ uint32_t smem_u32(const void* p) {
    uint32_t a;
    asm("{ .reg .u64 t; cvta.to.shared.u64 t, %1; cvt.u32.u64 %0, t; }" : "=r"(a) : "l"(p));
    return a;
}
__device__ __forceinline__ void ldsm4(uint32_t addr, uint32_t& r0, uint32_t& r1, uint32_t& r2, uint32_t& r3) {
    asm volatile("ldmatrix.sync.aligned.m8n8.x4.shared.b16 {%0,%1,%2,%3}, [%4];"
                 : "=r"(r0), "=r"(r1), "=r"(r2), "=r"(r3) : "r"(addr));
}
__device__ __forceinline__ void mma_bf16(float c[4], const uint32_t a[4], uint32_t b0, uint32_t b1) {
    asm volatile(
        "mma.sync.aligned.m16n8k16.row.col.f32.bf16.bf16.f32 "
        "{%0,%1,%2,%3}, {%4,%5,%6,%7}, {%8,%9}, {%0,%1,%2,%3};"
        : "+f"(c[0]), "+f"(c[1]), "+f"(c[2]), "+f"(c[3])
        : "r"(a[0]), "r"(a[1]), "r"(a[2]), "r"(a[3]), "r"(b0), "r"(b1));
}
__device__ __forceinline__ void splitf2(float x, float y, uint32_t& h, uint32_t& l) {
    __nv_bfloat162 hh = __float22bfloat162_rn(make_float2(x, y));
    float2 hf = __bfloat1622float2(hh);
    __nv_bfloat162 ll = __float22bfloat162_rn(make_float2(x - hf.x, y - hf.y));
    h = *(uint32_t*)&hh; l = *(uint32_t*)&ll;
}
__device__ __forceinline__ void split2(float4 v, uint2& hi, uint2& lo) {
    uint32_t h0, l0, h1, l1;
    splitf2(v.x, v.y, h0, l0);
    splitf2(v.z, v.w, h1, l1);
    hi = make_uint2(h0, h1);
    lo = make_uint2(l0, l1);
}
#define CP_ASYNC16(dst, src) asm volatile("cp.async.cg.shared.global [%0], [%1], 16;" :: "r"(dst), "l"(src) : "memory")
#define CP_COMMIT()          asm volatile("cp.async.commit_group;" ::: "memory")
#define CP_WAIT0()           asm volatile("cp.async.wait_group 0;" ::: "memory")
#define CP_WAIT1()           asm volatile("cp.async.wait_group 1;" ::: "memory")

// -------------------- fp32 -> bf16 hi/lo split --------------------
__global__ __launch_bounds__(256) void split_w(
    bf16* __restrict__ H, bf16* __restrict__ L, const float* __restrict__ W, int n)
{
    int i = (blockIdx.x * 256 + threadIdx.x) * 4;
    if (i < n) {
        float4 v = *(const float4*)(W + i);
        uint2 h, l; split2(v, h, l);
        *(uint2*)(H + i) = h;
        *(uint2*)(L + i) = l;
    }
}

// -------------------- fold 3-tap conv into weight columns, then split ------------
// Wfold[m,k] = w0*W[m,k+1] + w1*W[m,k] + w2*W[m,k-1]  (zero pad) — so that
// x @ Wfold^T == conv(x) @ W^T with conv y[c] = w0*x[c-1]+w1*x[c]+w2*x[c+1].
__global__ __launch_bounds__(128) void fold_split(
    bf16* __restrict__ H, bf16* __restrict__ L,
    const float* __restrict__ W, const float* __restrict__ w)
{
    __shared__ float rb[D];
    const int row = blockIdx.x, t = threadIdx.x;
    float4 v = *(const float4*)(W + (size_t)row * D + t * 4);
    *(float4*)&rb[t * 4] = v;
    __syncthreads();
    const float w0 = w[0], w1 = w[1], w2 = w[2];
    float y[4];
    #pragma unroll
    for (int i = 0; i < 4; i++) {
        int c = t * 4 + i;
        float xm = (c > 0) ? rb[c - 1] : 0.f;       // coeff w2
        float xp = (c < D - 1) ? rb[c + 1] : 0.f;   // coeff w0
        y[i] = w2 * xm + w1 * rb[c] + w0 * xp;
    }
    uint32_t h0, l0, h1, l1;
    splitf2(y[0], y[1], h0, l0);
    splitf2(y[2], y[3], h1, l1);
    *(uint2*)(H + (size_t)row * D + t * 4) = make_uint2(h0, h1);
    *(uint2*)(L + (size_t)row * D + t * 4) = make_uint2(l0, l1);
}

// ==================== single-stage streamed split-bf16 mma GEMM, 2 CTAs/SM ========
#define T_AH 0
#define T_AL 18432
#define T_BH 36864
#define T_BL 55296
#define TCG_SMEM 73728

__global__ __launch_bounds__(256, 2) void mma_gemm(
    float* __restrict__ C, bf16* __restrict__ Ch, bf16* __restrict__ Cl,
    const bf16* __restrict__ Ah, const bf16* __restrict__ Al,
    const bf16* __restrict__ Bh, const bf16* __restrict__ Bl,
    int M, int Nt, int K, const float* __restrict__ bias, int act)
{
    extern __shared__ char smem[];
    const uint32_t sb = smem_u32(smem);
    const int tid = threadIdx.x, wid = tid >> 5, lane = tid & 31;
    const int m0 = blockIdx.y * 128, n0 = blockIdx.x * 128;
    const int wm = (wid & 3) << 5;
    const int wn = (wid >> 2) << 6;
    const int quad = lane >> 3, r = lane & 7;
    const int arow = ((quad & 1) << 3) + r, ak = (quad >> 1) << 3;
    const int brow = ((quad >> 1) << 3) + r, bk = (quad & 1) << 3;

    float acc[2][8][4];
    #pragma unroll
    for (int i = 0; i < 2; i++)
        #pragma unroll
        for (int j = 0; j < 8; j++)
            #pragma unroll
            for (int q = 0; q < 4; q++) acc[i][j][q] = 0.f;

    const int nit = K >> 6;

    #pragma unroll
    for (int j = 0; j < 4; j++) {
        int ch = tid + (j << 8);
        int row = ch >> 3, cc = ch & 7;
        uint32_t so = row * 144 + cc * 16;
        size_t ga = (size_t)(m0 + row) * K + cc * 8;
        size_t gb = (size_t)(n0 + row) * K + cc * 8;
        CP_ASYNC16(sb + T_AH + so, Ah + ga);
        CP_ASYNC16(sb + T_AL + so, Al + ga);
        CP_ASYNC16(sb + T_BH + so, Bh + gb);
        CP_ASYNC16(sb + T_BL + so, Bl + gb);
    }
    CP_COMMIT();

    for (int it = 0; it < nit; it++) {
        CP_WAIT0();
        __syncthreads();
        #pragma unroll
        for (int kc = 0; kc < 4; kc++) {
            uint32_t ah[2][4], al[2][4];
            #pragma unroll
            for (int i = 0; i < 2; i++) {
                uint32_t ao = sb + (wm + (i << 4) + arow) * 144 + ((kc << 4) + ak) * 2;
                ldsm4(ao + T_AH, ah[i][0], ah[i][1], ah[i][2], ah[i][3]);
                ldsm4(ao + T_AL, al[i][0], al[i][1], al[i][2], al[i][3]);
            }
            #pragma unroll
            for (int jj = 0; jj < 4; jj++) {
                uint32_t bo = sb + (wn + (jj << 4) + brow) * 144 + ((kc << 4) + bk) * 2;
                uint32_t bh0, bh1, bh2, bh3, bl0, bl1, bl2, bl3;
                ldsm4(bo + T_BH, bh0, bh1, bh2, bh3);
                ldsm4(bo + T_BL, bl0, bl1, bl2, bl3);
                #pragma unroll
                for (int i = 0; i < 2; i++) {
                    mma_bf16(acc[i][2 * jj],     ah[i], bh0, bh1);
                    mma_bf16(acc[i][2 * jj],     ah[i], bl0, bl1);
                    mma_bf16(acc[i][2 * jj],     al[i], bh0, bh1);
                    mma_bf16(acc[i][2 * jj + 1], ah[i], bh2, bh3);
                    mma_bf16(acc[i][2 * jj + 1], ah[i], bl2, bl3);
                    mma_bf16(acc[i][2 * jj + 1], al[i], bh2, bh3);
                }
            }
        }
        __syncthreads();
        if (it + 1 < nit) {
            const int k0 = (it + 1) << 6;
            #pragma unroll
            for (int j = 0; j < 4; j++) {
                int ch = tid + (j << 8);
                int row = ch >> 3, cc = ch & 7;
                uint32_t so = row * 144 + cc * 16;
                size_t ga = (size_t)(m0 + row) * K + k0 + cc * 8;
                size_t gb = (size_t)(n0 + row) * K + k0 + cc * 8;
                CP_ASYNC16(sb + T_AH + so, Ah + ga);
                CP_ASYNC16(sb + T_AL + so, Al + ga);
                CP_ASYNC16(sb + T_BH + so, Bh + gb);
                CP_ASYNC16(sb + T_BL + so, Bl + gb);
            }
            CP_COMMIT();
        }
    }

    const int g = lane >> 2, tg = (lane & 3) << 1;
    #pragma unroll
    for (int i = 0; i < 2; i++) {
        const int row0 = m0 + wm + (i << 4) + g;
        #pragma unroll
        for (int j = 0; j < 8; j++) {
            const int col = n0 + wn + (j << 3) + tg;
            float b0 = 0.f, b1 = 0.f;
            if (bias) { b0 = bias[col]; b1 = bias[col + 1]; }
            float v0 = acc[i][j][0] + b0, v1 = acc[i][j][1] + b1;
            float v2 = acc[i][j][2] + b0, v3 = acc[i][j][3] + b1;
            if (act) {
                v0 = 0.5f * v0 * (1.0f + erff(v0 * 0.70710678118654752f));
                v1 = 0.5f * v1 * (1.0f + erff(v1 * 0.70710678118654752f));
                v2 = 0.5f * v2 * (1.0f + erff(v2 * 0.70710678118654752f));
                v3 = 0.5f * v3 * (1.0f + erff(v3 * 0.70710678118654752f));
            }
            if (C) {
                *(float2*)(C + (size_t)row0 * Nt + col) = make_float2(v0, v1);
                *(float2*)(C + (size_t)(row0 + 8) * Nt + col) = make_float2(v2, v3);
            }
            if (Ch) {
                uint32_t h0, l0, h1, l1;
                splitf2(v0, v1, h0, l0);
                splitf2(v2, v3, h1, l1);
                *(uint32_t*)(Ch + (size_t)row0 * Nt + col) = h0;
                *(uint32_t*)(Ch + (size_t)(row0 + 8) * Nt + col) = h1;
                if (Cl) {
                    *(uint32_t*)(Cl + (size_t)row0 * Nt + col) = l0;
                    *(uint32_t*)(Cl + (size_t)(row0 + 8) * Nt + col) = l1;
                }
            }
        }
    }
}

// -------------------- GEMM NN (fp32, tiny: weight folding) --------------------
__global__ __launch_bounds__(256) void gemm_nn(
    float* __restrict__ C, const float* __restrict__ A, const float* __restrict__ B,
    int M, int N, int K)
{
    __shared__ float As[16][64];
    __shared__ float Bs[16][64];
    const int tid = threadIdx.x;
    const int tx = tid & 15, ty = tid >> 4;
    const int lr = tid >> 2, lc = (tid & 3) << 2;
    const int bkr = tid >> 4, bnc = (tid & 15) << 2;
    const float* Ab = A + (size_t)blockIdx.y * 64 * K;
    float acc[4][4] = {};
    for (int k0 = 0; k0 < K; k0 += 16) {
        float4 a4 = *(const float4*)(Ab + (size_t)lr * K + k0 + lc);
        float4 b4 = *(const float4*)(B + (size_t)(k0 + bkr) * N + blockIdx.x * 64 + bnc);
        __syncthreads();
        As[lc + 0][lr] = a4.x; As[lc + 1][lr] = a4.y; As[lc + 2][lr] = a4.z; As[lc + 3][lr] = a4.w;
        *(float4*)&Bs[bkr][bnc] = b4;
        __syncthreads();
        #pragma unroll
        for (int k = 0; k < 16; k++) {
            float4 av = *(const float4*)&As[k][ty << 2];
            float4 bv = *(const float4*)&Bs[k][tx << 2];
            float a[4] = {av.x, av.y, av.z, av.w};
            float b[4] = {bv.x, bv.y, bv.z, bv.w};
            #pragma unroll
            for (int i = 0; i < 4; i++)
                #pragma unroll
                for (int j = 0; j < 4; j++) acc[i][j] += a[i] * b[j];
        }
    }
    #pragma unroll
    for (int i = 0; i < 4; i++) {
        int m = blockIdx.y * 64 + (ty << 2) + i;
        #pragma unroll
        for (int j = 0; j < 4; j++)
            C[(size_t)m * N + blockIdx.x * 64 + (tx << 2) + j] = acc[i][j];
    }
}

// ==================== tensor-core flash attention (K/V from merged KV, stride 1024) =
#define AQ_H 0
#define AQ_L 18432
#define AK_B(s) (36864 + (s) * 18432)
#define AVT  73728
#define AT_SMEM 82944

__global__ __launch_bounds__(256, 1) void attn_mma(
    bf16* __restrict__ Oh, bf16* __restrict__ Ol,
    const bf16* __restrict__ Qh, const bf16* __restrict__ Ql,
    const bf16* __restrict__ Kh, const bf16* __restrict__ Kl,
    const bf16* __restrict__ Vb)
{
    extern __shared__ char smem[];
    const uint32_t sb = smem_u32(smem);
    const int tid = threadIdx.x, wid = tid >> 5, lane = tid & 31;
    const int b = blockIdx.z, h = blockIdx.y;
    const int q0 = blockIdx.x * 128;
    const size_t tok0 = (size_t)b * SEQL;
    const int hc = h * 64;
    const int quad = lane >> 3, r = lane & 7;
    const int arow = ((quad & 1) << 3) + r, ak = (quad >> 1) << 3;
    const int brow = ((quad >> 1) << 3) + r, bk = (quad & 1) << 3;
    const int g = lane >> 2, tg = lane & 3;
    const int wq0 = wid << 4;

    {
        #pragma unroll
        for (int j = 0; j < 4; j++) {
            int ch = tid + (j << 8);
            int row = ch >> 3, cc = ch & 7;
            uint32_t so = row * 144 + cc * 16;
            size_t ga = (tok0 + q0 + row) * D + hc + cc * 8;
            CP_ASYNC16(sb + AQ_H + so, Qh + ga);
            CP_ASYNC16(sb + AQ_L + so, Ql + ga);
        }
        #pragma unroll
        for (int j = 0; j < 2; j++) {
            int ch = tid + (j << 8);
            int row = ch >> 3, cc = ch & 7;
            uint32_t so = row * 144 + cc * 16;
            size_t ga = (tok0 + row) * KVD + hc + cc * 8;
            CP_ASYNC16(sb + AK_B(0) + so, Kh + ga);
            CP_ASYNC16(sb + AK_B(0) + 9216 + so, Kl + ga);
        }
        CP_COMMIT();
    }
    uint4 vr[2];
    #pragma unroll
    for (int j = 0; j < 2; j++) {
        int ch = tid + (j << 8);
        int row = ch >> 3, cc = ch & 7;
        vr[j] = *(const uint4*)(Vb + (tok0 + row) * KVD + hc + cc * 8);
    }

    float o[8][4];
    #pragma unroll
    for (int j = 0; j < 8; j++)
        #pragma unroll
        for (int q = 0; q < 4; q++) o[j][q] = 0.f;
    float m0r = -1e30f, m1r = -1e30f, l0r = 0.f, l1r = 0.f;

    for (int kt = 0; kt < SEQL / 64; kt++) {
        const int s = kt & 1;
        if (kt + 1 < SEQL / 64) {
            const size_t kb = tok0 + (size_t)(kt + 1) * 64;
            #pragma unroll
            for (int j = 0; j < 2; j++) {
                int ch = tid + (j << 8);
                int row = ch >> 3, cc = ch & 7;
                uint32_t so = row * 144 + cc * 16;
                size_t ga = (kb + row) * KVD + hc + cc * 8;
                CP_ASYNC16(sb + AK_B(1 - s) + so, Kh + ga);
                CP_ASYNC16(sb + AK_B(1 - s) + 9216 + so, Kl + ga);
            }
            CP_COMMIT();
        }
        #pragma unroll
        for (int j = 0; j < 2; j++) {
            int ch = tid + (j << 8);
            int row = ch >> 3, cc = ch & 7;
            const bf16* pv = (const bf16*)&vr[j];
            #pragma unroll
            for (int e = 0; e < 8; e++) {
                int d = cc * 8 + e;
                *(bf16*)(smem + AVT + d * 144 + row * 2) = pv[e];
            }
        }
        if (kt + 1 < SEQL / 64) { CP_WAIT1(); } else { CP_WAIT0(); }
        __syncthreads();
        if (kt + 1 < SEQL / 64) {
            const size_t kb = tok0 + (size_t)(kt + 1) * 64;
            #pragma unroll
            for (int j = 0; j < 2; j++) {
                int ch = tid + (j << 8);
                int row = ch >> 3, cc = ch & 7;
                vr[j] = *(const uint4*)(Vb + (kb + row) * KVD + hc + cc * 8);
            }
        }
        float sc[8][4];
        #pragma unroll
        for (int j = 0; j < 8; j++)
            #pragma unroll
            for (int q = 0; q < 4; q++) sc[j][q] = 0.f;
        #pragma unroll
        for (int kc = 0; kc < 4; kc++) {
            uint32_t ah[4], al[4];
            uint32_t ao = sb + (wq0 + arow) * 144 + ((kc << 4) + ak) * 2;
            ldsm4(ao + AQ_H, ah[0], ah[1], ah[2], ah[3]);
            ldsm4(ao + AQ_L, al[0], al[1], al[2], al[3]);
            #pragma unroll
            for (int jj = 0; jj < 4; jj++) {
                uint32_t bo = sb + AK_B(s) + ((jj << 4) + brow) * 144 + ((kc << 4) + bk) * 2;
                uint32_t bh0, bh1, bh2, bh3, bl0, bl1, bl2, bl3;
                ldsm4(bo, bh0, bh1, bh2, bh3);
                ldsm4(bo + 9216, bl0, bl1, bl2, bl3);
                mma_bf16(sc[2 * jj],     ah, bh0, bh1);
                mma_bf16(sc[2 * jj],     ah, bl0, bl1);
                mma_bf16(sc[2 * jj],     al, bh0, bh1);
                mma_bf16(sc[2 * jj + 1], ah, bh2, bh3);
                mma_bf16(sc[2 * jj + 1], ah, bl2, bl3);
                mma_bf16(sc[2 * jj + 1], al, bh2, bh3);
            }
        }
        float mx0 = -1e30f, mx1 = -1e30f;
        #pragma unroll
        for (int j = 0; j < 8; j++) {
            sc[j][0] *= ATT_SCALE; sc[j][1] *= ATT_SCALE;
            sc[j][2] *= ATT_SCALE; sc[j][3] *= ATT_SCALE;
            mx0 = fmaxf(mx0, fmaxf(sc[j][0], sc[j][1]));
            mx1 = fmaxf(mx1, fmaxf(sc[j][2], sc[j][3]));
        }
        mx0 = fmaxf(mx0, __shfl_xor_sync(0xffffffffu, mx0, 1));
        mx0 = fmaxf(mx0, __shfl_xor_sync(0xffffffffu, mx0, 2));
        mx1 = fmaxf(mx1, __shfl_xor_sync(0xffffffffu, mx1, 1));
        mx1 = fmaxf(mx1, __shfl_xor_sync(0xffffffffu, mx1, 2));
        float mn0 = fmaxf(m0r, mx0), mn1 = fmaxf(m1r, mx1);
        float a0 = __expf(m0r - mn0), a1 = __expf(m1r - mn1);
        m0r = mn0; m1r = mn1;
        float rs0 = 0.f, rs1 = 0.f;
        #pragma unroll
        for (int j = 0; j < 8; j++) {
            sc[j][0] = __expf(sc[j][0] - mn0); sc[j][1] = __expf(sc[j][1] - mn0);
            sc[j][2] = __expf(sc[j][2] - mn1); sc[j][3] = __expf(sc[j][3] - mn1);
            rs0 += sc[j][0] + sc[j][1];
            rs1 += sc[j][2] + sc[j][3];
        }
        rs0 += __shfl_xor_sync(0xffffffffu, rs0, 1);
        rs0 += __shfl_xor_sync(0xffffffffu, rs0, 2);
        rs1 += __shfl_xor_sync(0xffffffffu, rs1, 1);
        rs1 += __shfl_xor_sync(0xffffffffu, rs1, 2);
        l0r = l0r * a0 + rs0;
        l1r = l1r * a1 + rs1;
        #pragma unroll
        for (int j = 0; j < 8; j++) {
            o[j][0] *= a0; o[j][1] *= a0; o[j][2] *= a1; o[j][3] *= a1;
        }
        #pragma unroll
        for (int kk = 0; kk < 4; kk++) {
            uint32_t pa[4];
            __nv_bfloat162 t0 = __float22bfloat162_rn(make_float2(sc[2 * kk][0], sc[2 * kk][1]));
            __nv_bfloat162 t1 = __float22bfloat162_rn(make_float2(sc[2 * kk][2], sc[2 * kk][3]));
            __nv_bfloat162 t2 = __float22bfloat162_rn(make_float2(sc[2 * kk + 1][0], sc[2 * kk + 1][1]));
            __nv_bfloat162 t3 = __float22bfloat162_rn(make_float2(sc[2 * kk + 1][2], sc[2 * kk + 1][3]));
            pa[0] = *(uint32_t*)&t0; pa[1] = *(uint32_t*)&t1;
            pa[2] = *(uint32_t*)&t2; pa[3] = *(uint32_t*)&t3;
            #pragma unroll
            for (int jj = 0; jj < 4; jj++) {
                uint32_t bo = sb + AVT + ((jj << 4) + brow) * 144 + ((kk << 4) + bk) * 2;
                uint32_t b0, b1, b2, b3;
                ldsm4(bo, b0, b1, b2, b3);
                mma_bf16(o[2 * jj],     pa, b0, b1);
                mma_bf16(o[2 * jj + 1], pa, b2, b3);
            }
        }
        __syncthreads();
    }
    const float inv0 = 1.0f / l0r, inv1 = 1.0f / l1r;
    #pragma unroll
    for (int j = 0; j < 8; j++) {
        int col = hc + (j << 3) + (tg << 1);
        size_t r0 = (tok0 + q0 + wq0 + g) * D + col;
        size_t r1 = (tok0 + q0 + wq0 + g + 8) * D + col;
        uint32_t h0, l0, h1, l1;
        splitf2(o[j][0] * inv0, o[j][1] * inv0, h0, l0);
        splitf2(o[j][2] * inv1, o[j][3] * inv1, h1, l1);
        *(uint32_t*)(Oh + r0) = h0; *(uint32_t*)(Ol + r0) = l0;
        *(uint32_t*)(Oh + r1) = h1; *(uint32_t*)(Ol + r1) = l1;
    }
}

// -------------------- LN(a+b)*g+be; fp32 + optional split bf16 + hn --------------
__global__ __launch_bounds__(128) void ln_kernel(
    float* __restrict__ out, bf16* __restrict__ outH, bf16* __restrict__ outL,
    const float* __restrict__ a, const float* __restrict__ b,
    const float* __restrict__ g, const float* __restrict__ be,
    float* __restrict__ hn_out, int do_hn)
{
    __shared__ float sh[8];
    const int row = blockIdx.x, t = threadIdx.x;
    float4 av = *(const float4*)(a + (size_t)row * D + t * 4);
    float4 bv = *(const float4*)(b + (size_t)row * D + t * 4);
    float v[4] = {av.x + bv.x, av.y + bv.y, av.z + bv.z, av.w + bv.w};
    float s = v[0] + v[1] + v[2] + v[3];
    float s2 = v[0] * v[0] + v[1] * v[1] + v[2] * v[2] + v[3] * v[3];
    #pragma unroll
    for (int off = 16; off; off >>= 1) {
        s += __shfl_xor_sync(0xffffffffu, s, off);
        s2 += __shfl_xor_sync(0xffffffffu, s2, off);
    }
    if ((t & 31) == 0) { sh[t >> 5] = s; sh[4 + (t >> 5)] = s2; }
    __syncthreads();
    s = sh[0] + sh[1] + sh[2] + sh[3];
    s2 = sh[4] + sh[5] + sh[6] + sh[7];
    const float mean = s * (1.0f / D);
    const float rstd = rsqrtf(s2 * (1.0f / D) - mean * mean + 1e-5f);
    float4 gv = *(const float4*)(g + t * 4);
    float4 bev = *(const float4*)(be + t * 4);
    float y[4];
    y[0] = (v[0] - mean) * rstd * gv.x + bev.x;
    y[1] = (v[1] - mean) * rstd * gv.y + bev.y;
    y[2] = (v[2] - mean) * rstd * gv.z + bev.z;
    y[3] = (v[3] - mean) * rstd * gv.w + bev.w;
    if (out)
        *(float4*)(out + (size_t)row * D + t * 4) = make_float4(y[0], y[1], y[2], y[3]);
    if (outH) {
        uint32_t h0, l0, h1, l1;
        splitf2(y[0], y[1], h0, l0);
        splitf2(y[2], y[3], h1, l1);
        *(uint2*)(outH + (size_t)row * D + t * 4) = make_uint2(h0, h1);
        *(uint2*)(outL + (size_t)row * D + t * 4) = make_uint2(l0, l1);
    }
    if (do_hn && (row & (SEQL - 1)) == SEQL - 1)
        *(float4*)(hn_out + (size_t)(row >> 10) * D + t * 4) = av;
}

// -------------------- launch --------------------
extern "C" void kernel_launch(void* const* d_in, const int* in_sizes, int n_in,
                              void* d_out, int out_size)
{
    const float* input   = (const float*)d_in[0];
    const float* wq_c    = (const float*)d_in[3];
    const float* fc_c    = (const float*)d_in[5];
    const float* wq_g    = (const float*)d_in[6];
    const float* wk_g    = (const float*)d_in[7];
    const float* fc_g    = (const float*)d_in[8];
    const float* wq_x    = (const float*)d_in[9];
    const float* fc_x    = (const float*)d_in[11];
    const float* conv1_w = (const float*)d_in[12];
    const float* conv2_w = (const float*)d_in[13];
    const float* ln1_g = (const float*)d_in[14];
    const float* ln1_b = (const float*)d_in[15];
    const float* ln2_g = (const float*)d_in[16];
    const float* ln2_b = (const float*)d_in[17];
    const float* ln3_g = (const float*)d_in[18];
    const float* ln3_b = (const float*)d_in[19];
    const float* ln4_g = (const float*)d_in[20];
    const float* ln4_b = (const float*)d_in[21];
    const float* mlp_w1 = (const float*)d_in[22];
    const float* mlp_b1 = (const float*)d_in[23];
    const float* mlp_w2 = (const float*)d_in[24];
    const float* mlp_b2 = (const float*)d_in[25];

    float *M1, *M3, *B0, *B1, *B2, *B3, *B4;
    bf16 *Wh, *Wl, *XH, *XL, *KVH, *KVL, *QH, *QL;
    bf16 *ATH, *ATL, *X1H, *X1L, *X2H, *X2L, *X3H, *X3L, *HIDH, *HIDL;
    cudaGetSymbolAddress((void**)&M1, d_M1);
    cudaGetSymbolAddress((void**)&M3, d_M3);
    cudaGetSymbolAddress((void**)&B0, d_B0);
    cudaGetSymbolAddress((void**)&B1, d_B1);
    cudaGetSymbolAddress((void**)&B2, d_B2);
    cudaGetSymbolAddress((void**)&B3, d_B3);
    cudaGetSymbolAddress((void**)&B4, d_B4);
    cudaGetSymbolAddress((void**)&Wh, d_Wh);
    cudaGetSymbolAddress((void**)&Wl, d_Wl);
    cudaGetSymbolAddress((void**)&XH, d_XH);
    cudaGetSymbolAddress((void**)&XL, d_XL);
    cudaGetSymbolAddress((void**)&KVH, d_KVH);
    cudaGetSymbolAddress((void**)&KVL, d_KVL);
    cudaGetSymbolAddress((void**)&QH, d_QH);
    cudaGetSymbolAddress((void**)&QL, d_QL);
    cudaGetSymbolAddress((void**)&ATH, d_ATH);
    cudaGetSymbolAddress((void**)&ATL, d_ATL);
    cudaGetSymbolAddress((void**)&X1H, d_X1H);
    cudaGetSymbolAddress((void**)&X1L, d_X1L);
    cudaGetSymbolAddress((void**)&X2H, d_X2H);
    cudaGetSymbolAddress((void**)&X2L, d_X2L);
    cudaGetSymbolAddress((void**)&X3H, d_X3H);
    cudaGetSymbolAddress((void**)&X3L, d_X3L);
    cudaGetSymbolAddress((void**)&HIDH, d_HIDH);
    cudaGetSymbolAddress((void**)&HIDL, d_HIDL);

    cudaFuncSetAttribute(mma_gemm, cudaFuncAttributeMaxDynamicSharedMemorySize, TCG_SMEM);
    cudaFuncSetAttribute(attn_mma, cudaFuncAttributeMaxDynamicSharedMemorySize, AT_SMEM);

    float* outp = (float*)d_out;
    const size_t out_main = (size_t)N_TOK * D;
    float* hnp = outp + out_main;
    int do_hn = (out_size >= (int)(out_main + BSZ * D)) ? 1 : 0;
    if (!do_hn) hnp = outp;

    const dim3 blk(256);
    const dim3 tg512(D / 128, N_TOK / 128);       // (4, 128)
    const dim3 tg1024(KVD / 128, N_TOK / 128);    // (8, 128)
    const dim3 tg2048(DFF / 128, N_TOK / 128);    // (16, 128)
    const dim3 gW(D / 64, D / 64);
    const int nW512 = D * D / 1024;
    const int nW2048 = D * DFF / 1024;
    const int nX = N_TOK * D / 1024;

    // ---- prep: weight folding + splits (one-time per call) ----
    gemm_nn<<<gW, blk>>>(M1, fc_c, wq_c, D, D, D);       // M1 = fc_c @ wq_c
    gemm_nn<<<gW, blk>>>(M3, fc_x, wq_x, D, D, D);       // M3 = fc_x @ wq_x
    split_w<<<nW512, blk>>>(Wh + OFF_WKG, Wl + OFF_WKG, wk_g, D * D);
    split_w<<<nW512, blk>>>(Wh + OFF_WQG, Wl + OFF_WQG, wq_g, D * D);
    split_w<<<nX, blk>>>(XH, XL, input, N_TOK * D);
    fold_split<<<D, 128>>>(Wh + OFF_M1, Wl + OFF_M1, M1, conv1_w);       // conv1 folded into M1
    fold_split<<<D, 128>>>(Wh + OFF_WQG2, Wl + OFF_WQG2, wq_g, conv2_w); // conv2 folded into wq_g
    split_w<<<nW512, blk>>>(Wh + OFF_FCG, Wl + OFF_FCG, fc_g, D * D);
    split_w<<<nW512, blk>>>(Wh + OFF_M3, Wl + OFF_M3, M3, D * D);
    split_w<<<nW2048, blk>>>(Wh + OFF_W1, Wl + OFF_W1, mlp_w1, D * DFF);
    split_w<<<nW2048, blk>>>(Wh + OFF_W2, Wl + OFF_W2, mlp_w2, D * DFF);

    // ---- merged Kg|Vg projection: KV[:, 0:512]=X@wk_g^T, KV[:, 512:1024]=X@wq_g^T
    mma_gemm<<<tg1024, blk, TCG_SMEM>>>(nullptr, KVH, KVL, XH, XL,
                                        Wh + OFF_WKG, Wl + OFF_WKG, N_TOK, KVD, D, nullptr, 0);

    // ---- u = X @ M1c^T (conv1 folded); x1 = LN1(u + input)
    mma_gemm<<<tg512, blk, TCG_SMEM>>>(B1, nullptr, nullptr, XH, XL,
                                       Wh + OFF_M1, Wl + OFF_M1, N_TOK, D, D, nullptr, 0);
    ln_kernel<<<N_TOK, 128>>>(B2, X1H, X1L, B1, input, ln1_g, ln1_b, hnp, 0);

    // ---- Q = x1 @ Wqg2^T (conv2 folded); attention; g = att @ fc_g^T; x2 = LN2(g + x1)
    mma_gemm<<<tg512, blk, TCG_SMEM>>>(nullptr, QH, QL, X1H, X1L,
                                       Wh + OFF_WQG2, Wl + OFF_WQG2, N_TOK, D, D, nullptr, 0);
    attn_mma<<<dim3(SEQL / 128, 8, BSZ), blk, AT_SMEM>>>(ATH, ATL, QH, QL, KVH, KVL, KVH + 512);
    mma_gemm<<<tg512, blk, TCG_SMEM>>>(B0, nullptr, nullptr, ATH, ATL,
                                       Wh + OFF_FCG, Wl + OFF_FCG, N_TOK, D, D, nullptr, 0);
    ln_kernel<<<N_TOK, 128>>>(B3, X2H, X2L, B0, B2, ln2_g, ln2_b, hnp, 0);

    // ---- h = x2 @ M3^T; x3 = LN3(h + x2); hn = raw h of last token
    mma_gemm<<<tg512, blk, TCG_SMEM>>>(B1, nullptr, nullptr, X2H, X2L,
                                       Wh + OFF_M3, Wl + OFF_M3, N_TOK, D, D, nullptr, 0);
    ln_kernel<<<N_TOK, 128>>>(B4, X3H, X3L, B1, B3, ln3_g, ln3_b, hnp, do_hn);

    // ---- MLP: hid = gelu(x3 @ w1^T + b1); y = hid @ w2^T + b2; out = LN4(y + x3)
    mma_gemm<<<tg2048, blk, TCG_SMEM>>>(nullptr, HIDH, HIDL, X3H, X3L,
                                        Wh + OFF_W1, Wl + OFF_W1, N_TOK, DFF, D, mlp_b1, 1);
    mma_gemm<<<tg512, blk, TCG_SMEM>>>(B0, nullptr, nullptr, HIDH, HIDL,
                                       Wh + OFF_W2, Wl + OFF_W2, N_TOK, D, DFF, mlp_b2, 0);
    ln_kernel<<<N_TOK, 128>>>(outp, nullptr, nullptr, B0, B4, ln4_g, ln4_b, hnp, 0);
}

// round 14
// speedup vs baseline: 1.1409x; 1.0600x over previous
#include <cuda_runtime.h>
#include <cuda_bf16.h>
#include <math.h>
#include <stdint.h>

#define N_TOK 16384
#define D 512
#define SEQL 1024
#define BSZ 16
#define DFF 2048
#define KVD 1024
#define ATT_SCALE 0.125f

typedef __nv_bfloat16 bf16;

// -------------------- fp32 scratch --------------------
__device__ float d_M1[D * D];
__device__ float d_M3[D * D];
__device__ float d_B0[(size_t)N_TOK * D];
__device__ float d_B1[(size_t)N_TOK * D];

// -------------------- split-bf16 weights (wkg|wqg|M1c contiguous for merged GEMM) --
#define OFF_WKG  0
#define OFF_WQG  262144
#define OFF_M1   524288
#define OFF_FCG  786432
#define OFF_M3   1048576
#define OFF_W1   1310720
#define OFF_W2   2359296
#define OFF_WQG2 3407872
#define W_TOTAL  3670016
__device__ bf16 d_Wh[W_TOTAL];
__device__ bf16 d_Wl[W_TOTAL];

// -------------------- split-bf16 activations --------------------
#define ACT_N ((size_t)N_TOK * D)
__device__ bf16 d_XH[ACT_N],   d_XL[ACT_N];
__device__ bf16 d_KVH[(size_t)N_TOK * KVD], d_KVL[(size_t)N_TOK * KVD];
__device__ bf16 d_QH[ACT_N],   d_QL[ACT_N];
__device__ bf16 d_ATH[ACT_N],  d_ATL[ACT_N];
__device__ bf16 d_X1H[ACT_N],  d_X1L[ACT_N];
__device__ bf16 d_X2H[ACT_N],  d_X2L[ACT_N];
__device__ bf16 d_X3H[ACT_N],  d_X3L[ACT_N];
__device__ bf16 d_HIDH[(size_t)N_TOK * DFF], d_HIDL[(size_t)N_TOK * DFF];

// ==================== helpers ====================
__device__ __forceinline__ uint32_t smem_u32(const void* p) {
    uint32_t a;
    asm("{ .reg .u64 t; cvta.to.shared.u64 t, %1; cvt.u32.u64 %0, t; }" : "=r"(a) : "l"(p));
    return a;
}
__device__ __forceinline__ void ldsm4(uint32_t addr, uint32_t& r0, uint32_t& r1, uint32_t& r2, uint32_t& r3) {
    asm volatile("ldmatrix.sync.aligned.m8n8.x4.shared.b16 {%0,%1,%2,%3}, [%4];"
                 : "=r"(r0), "=r"(r1), "=r"(r2), "=r"(r3) : "r"(addr));
}
__device__ __forceinline__ void ldsm4t(uint32_t addr, uint32_t& r0, uint32_t& r1, uint32_t& r2, uint32_t& r3) {
    asm volatile("ldmatrix.sync.aligned.m8n8.x4.trans.shared.b16 {%0,%1,%2,%3}, [%4];"
                 : "=r"(r0), "=r"(r1), "=r"(r2), "=r"(r3) : "r"(addr));
}
__device__ __forceinline__ void mma_bf16(float c[4], const uint32_t a[4], uint32_t b0, uint32_t b1) {
    asm volatile(
        "mma.sync.aligned.m16n8k16.row.col.f32.bf16.bf16.f32 "
        "{%0,%1,%2,%3}, {%4,%5,%6,%7}, {%8,%9}, {%0,%1,%2,%3};"
        : "+f"(c[0]), "+f"(c[1]), "+f"(c[2]), "+f"(c[3])
        : "r"(a[0]), "r"(a[1]), "r"(a[2]), "r"(a[3]), "r"(b0), "r"(b1));
}
__device__ __forceinline__ void splitf2(float x, float y, uint32_t& h, uint32_t& l) {
    __nv_bfloat162 hh = __float22bfloat162_rn(make_float2(x, y));
    float2 hf = __bfloat1622float2(hh);
    __nv_bfloat162 ll = __float22bfloat162_rn(make_float2(x - hf.x, y - hf.y));
    h = *(uint32_t*)&hh; l = *(uint32_t*)&ll;
}
__device__ __forceinline__ void split2(float4 v, uint2& hi, uint2& lo) {
    uint32_t h0, l0, h1, l1;
    splitf2(v.x, v.y, h0, l0);
    splitf2(v.z, v.w, h1, l1);
    hi = make_uint2(h0, h1);
    lo = make_uint2(l0, l1);
}
#define CP_ASYNC16(dst, src) asm volatile("cp.async.cg.shared.global [%0], [%1], 16;" :: "r"(dst), "l"(src) : "memory")
#define CP_COMMIT()          asm volatile("cp.async.commit_group;" ::: "memory")
#define CP_WAIT0()           asm volatile("cp.async.wait_group 0;" ::: "memory")
#define CP_WAIT1()           asm volatile("cp.async.wait_group 1;" ::: "memory")

// -------------------- fp32 -> bf16 hi/lo split --------------------
__global__ __launch_bounds__(256) void split_w(
    bf16* __restrict__ H, bf16* __restrict__ L, const float* __restrict__ W, int n)
{
    int i = (blockIdx.x * 256 + threadIdx.x) * 4;
    if (i < n) {
        float4 v = *(const float4*)(W + i);
        uint2 h, l; split2(v, h, l);
        *(uint2*)(H + i) = h;
        *(uint2*)(L + i) = l;
    }
}

// -------------------- fold 3-tap conv into weight columns, then split ------------
__global__ __launch_bounds__(128) void fold_split(
    bf16* __restrict__ H, bf16* __restrict__ L,
    const float* __restrict__ W, const float* __restrict__ w)
{
    __shared__ float rb[D];
    const int row = blockIdx.x, t = threadIdx.x;
    float4 v = *(const float4*)(W + (size_t)row * D + t * 4);
    *(float4*)&rb[t * 4] = v;
    __syncthreads();
    const float w0 = w[0], w1 = w[1], w2 = w[2];
    float y[4];
    #pragma unroll
    for (int i = 0; i < 4; i++) {
        int c = t * 4 + i;
        float xm = (c > 0) ? rb[c - 1] : 0.f;
        float xp = (c < D - 1) ? rb[c + 1] : 0.f;
        y[i] = w2 * xm + w1 * rb[c] + w0 * xp;
    }
    uint32_t h0, l0, h1, l1;
    splitf2(y[0], y[1], h0, l0);
    splitf2(y[2], y[3], h1, l1);
    *(uint2*)(H + (size_t)row * D + t * 4) = make_uint2(h0, h1);
    *(uint2*)(L + (size_t)row * D + t * 4) = make_uint2(l0, l1);
}

// ==================== single-stage streamed split-bf16 mma GEMM, 2 CTAs/SM ========
// mode 0: normal (C fp32 and/or Ch/Cl split, stride Nt).
// mode 1: merged KV|u — col<KVD: split store to Ch/Cl stride KVD; else fp32 to C at
//         row*D + (col-KVD).
#define T_AH 0
#define T_AL 18432
#define T_BH 36864
#define T_BL 55296
#define TCG_SMEM 73728

__global__ __launch_bounds__(256, 2) void mma_gemm(
    float* __restrict__ C, bf16* __restrict__ Ch, bf16* __restrict__ Cl,
    const bf16* __restrict__ Ah, const bf16* __restrict__ Al,
    const bf16* __restrict__ Bh, const bf16* __restrict__ Bl,
    int M, int Nt, int K, const float* __restrict__ bias, int act, int mode)
{
    extern __shared__ char smem[];
    const uint32_t sb = smem_u32(smem);
    const int tid = threadIdx.x, wid = tid >> 5, lane = tid & 31;
    const int m0 = blockIdx.y * 128, n0 = blockIdx.x * 128;
    const int wm = (wid & 3) << 5;
    const int wn = (wid >> 2) << 6;
    const int quad = lane >> 3, r = lane & 7;
    const int arow = ((quad & 1) << 3) + r, ak = (quad >> 1) << 3;
    const int brow = ((quad >> 1) << 3) + r, bk = (quad & 1) << 3;

    float acc[2][8][4];
    #pragma unroll
    for (int i = 0; i < 2; i++)
        #pragma unroll
        for (int j = 0; j < 8; j++)
            #pragma unroll
            for (int q = 0; q < 4; q++) acc[i][j][q] = 0.f;

    const int nit = K >> 6;

    #pragma unroll
    for (int j = 0; j < 4; j++) {
        int ch = tid + (j << 8);
        int row = ch >> 3, cc = ch & 7;
        uint32_t so = row * 144 + cc * 16;
        size_t ga = (size_t)(m0 + row) * K + cc * 8;
        size_t gb = (size_t)(n0 + row) * K + cc * 8;
        CP_ASYNC16(sb + T_AH + so, Ah + ga);
        CP_ASYNC16(sb + T_AL + so, Al + ga);
        CP_ASYNC16(sb + T_BH + so, Bh + gb);
        CP_ASYNC16(sb + T_BL + so, Bl + gb);
    }
    CP_COMMIT();

    for (int it = 0; it < nit; it++) {
        CP_WAIT0();
        __syncthreads();
        #pragma unroll
        for (int kc = 0; kc < 4; kc++) {
            uint32_t ah[2][4], al[2][4];
            #pragma unroll
            for (int i = 0; i < 2; i++) {
                uint32_t ao = sb + (wm + (i << 4) + arow) * 144 + ((kc << 4) + ak) * 2;
                ldsm4(ao + T_AH, ah[i][0], ah[i][1], ah[i][2], ah[i][3]);
                ldsm4(ao + T_AL, al[i][0], al[i][1], al[i][2], al[i][3]);
            }
            #pragma unroll
            for (int jj = 0; jj < 4; jj++) {
                uint32_t bo = sb + (wn + (jj << 4) + brow) * 144 + ((kc << 4) + bk) * 2;
                uint32_t bh0, bh1, bh2, bh3, bl0, bl1, bl2, bl3;
                ldsm4(bo + T_BH, bh0, bh1, bh2, bh3);
                ldsm4(bo + T_BL, bl0, bl1, bl2, bl3);
                #pragma unroll
                for (int i = 0; i < 2; i++) {
                    mma_bf16(acc[i][2 * jj],     ah[i], bh0, bh1);
                    mma_bf16(acc[i][2 * jj],     ah[i], bl0, bl1);
                    mma_bf16(acc[i][2 * jj],     al[i], bh0, bh1);
                    mma_bf16(acc[i][2 * jj + 1], ah[i], bh2, bh3);
                    mma_bf16(acc[i][2 * jj + 1], ah[i], bl2, bl3);
                    mma_bf16(acc[i][2 * jj + 1], al[i], bh2, bh3);
                }
            }
        }
        __syncthreads();
        if (it + 1 < nit) {
            const int k0 = (it + 1) << 6;
            #pragma unroll
            for (int j = 0; j < 4; j++) {
                int ch = tid + (j << 8);
                int row = ch >> 3, cc = ch & 7;
                uint32_t so = row * 144 + cc * 16;
                size_t ga = (size_t)(m0 + row) * K + k0 + cc * 8;
                size_t gb = (size_t)(n0 + row) * K + k0 + cc * 8;
                CP_ASYNC16(sb + T_AH + so, Ah + ga);
                CP_ASYNC16(sb + T_AL + so, Al + ga);
                CP_ASYNC16(sb + T_BH + so, Bh + gb);
                CP_ASYNC16(sb + T_BL + so, Bl + gb);
            }
            CP_COMMIT();
        }
    }

    const int g = lane >> 2, tg = (lane & 3) << 1;
    #pragma unroll
    for (int i = 0; i < 2; i++) {
        const int row0 = m0 + wm + (i << 4) + g;
        #pragma unroll
        for (int j = 0; j < 8; j++) {
            const int col = n0 + wn + (j << 3) + tg;
            float v0 = acc[i][j][0], v1 = acc[i][j][1];
            float v2 = acc[i][j][2], v3 = acc[i][j][3];
            if (mode == 1) {
                if (col < KVD) {
                    uint32_t h0, l0, h1, l1;
                    splitf2(v0, v1, h0, l0);
                    splitf2(v2, v3, h1, l1);
                    *(uint32_t*)(Ch + (size_t)row0 * KVD + col) = h0;
                    *(uint32_t*)(Ch + (size_t)(row0 + 8) * KVD + col) = h1;
                    *(uint32_t*)(Cl + (size_t)row0 * KVD + col) = l0;
                    *(uint32_t*)(Cl + (size_t)(row0 + 8) * KVD + col) = l1;
                } else {
                    *(float2*)(C + (size_t)row0 * D + col - KVD) = make_float2(v0, v1);
                    *(float2*)(C + (size_t)(row0 + 8) * D + col - KVD) = make_float2(v2, v3);
                }
                continue;
            }
            float b0 = 0.f, b1 = 0.f;
            if (bias) { b0 = bias[col]; b1 = bias[col + 1]; }
            v0 += b0; v1 += b1; v2 += b0; v3 += b1;
            if (act) {
                v0 = 0.5f * v0 * (1.0f + erff(v0 * 0.70710678118654752f));
                v1 = 0.5f * v1 * (1.0f + erff(v1 * 0.70710678118654752f));
                v2 = 0.5f * v2 * (1.0f + erff(v2 * 0.70710678118654752f));
                v3 = 0.5f * v3 * (1.0f + erff(v3 * 0.70710678118654752f));
            }
            if (C) {
                *(float2*)(C + (size_t)row0 * Nt + col) = make_float2(v0, v1);
                *(float2*)(C + (size_t)(row0 + 8) * Nt + col) = make_float2(v2, v3);
            }
            if (Ch) {
                uint32_t h0, l0, h1, l1;
                splitf2(v0, v1, h0, l0);
                splitf2(v2, v3, h1, l1);
                *(uint32_t*)(Ch + (size_t)row0 * Nt + col) = h0;
                *(uint32_t*)(Ch + (size_t)(row0 + 8) * Nt + col) = h1;
                if (Cl) {
                    *(uint32_t*)(Cl + (size_t)row0 * Nt + col) = l0;
                    *(uint32_t*)(Cl + (size_t)(row0 + 8) * Nt + col) = l1;
                }
            }
        }
    }
}

// -------------------- GEMM NN (fp32, tiny: weight folding) --------------------
__global__ __launch_bounds__(256) void gemm_nn(
    float* __restrict__ C, const float* __restrict__ A, const float* __restrict__ B,
    int M, int N, int K)
{
    __shared__ float As[16][64];
    __shared__ float Bs[16][64];
    const int tid = threadIdx.x;
    const int tx = tid & 15, ty = tid >> 4;
    const int lr = tid >> 2, lc = (tid & 3) << 2;
    const int bkr = tid >> 4, bnc = (tid & 15) << 2;
    const float* Ab = A + (size_t)blockIdx.y * 64 * K;
    float acc[4][4] = {};
    for (int k0 = 0; k0 < K; k0 += 16) {
        float4 a4 = *(const float4*)(Ab + (size_t)lr * K + k0 + lc);
        float4 b4 = *(const float4*)(B + (size_t)(k0 + bkr) * N + blockIdx.x * 64 + bnc);
        __syncthreads();
        As[lc + 0][lr] = a4.x; As[lc + 1][lr] = a4.y; As[lc + 2][lr] = a4.z; As[lc + 3][lr] = a4.w;
        *(float4*)&Bs[bkr][bnc] = b4;
        __syncthreads();
        #pragma unroll
        for (int k = 0; k < 16; k++) {
            float4 av = *(const float4*)&As[k][ty << 2];
            float4 bv = *(const float4*)&Bs[k][tx << 2];
            float a[4] = {av.x, av.y, av.z, av.w};
            float b[4] = {bv.x, bv.y, bv.z, bv.w};
            #pragma unroll
            for (int i = 0; i < 4; i++)
                #pragma unroll
                for (int j = 0; j < 4; j++) acc[i][j] += a[i] * b[j];
        }
    }
    #pragma unroll
    for (int i = 0; i < 4; i++) {
        int m = blockIdx.y * 64 + (ty << 2) + i;
        #pragma unroll
        for (int j = 0; j < 4; j++)
            C[(size_t)m * N + blockIdx.x * 64 + (tx << 2) + j] = acc[i][j];
    }
}

// ==================== tensor-core flash attention ====================
// Q/K pre-split; V plain bf16 cp.async'd row-major, PV B-frags via ldsm.trans.
#define AQ_H 0
#define AQ_L 18432
#define AK_B(s) (36864 + (s) * 18432)
#define AV_B(s) (73728 + (s) * 9216)
#define AT_SMEM 92160

__global__ __launch_bounds__(256, 1) void attn_mma(
    bf16* __restrict__ Oh, bf16* __restrict__ Ol,
    const bf16* __restrict__ Qh, const bf16* __restrict__ Ql,
    const bf16* __restrict__ Kh, const bf16* __restrict__ Kl,
    const bf16* __restrict__ Vb)
{
    extern __shared__ char smem[];
    const uint32_t sb = smem_u32(smem);
    const int tid = threadIdx.x, wid = tid >> 5, lane = tid & 31;
    const int b = blockIdx.z, h = blockIdx.y;
    const int q0 = blockIdx.x * 128;
    const size_t tok0 = (size_t)b * SEQL;
    const int hc = h * 64;
    const int quad = lane >> 3, r = lane & 7;
    const int arow = ((quad & 1) << 3) + r, ak = (quad >> 1) << 3;
    const int brow = ((quad >> 1) << 3) + r, bk = (quad & 1) << 3;
    const int vrow = (((lane >> 3) & 1) << 3) + (lane & 7);   // ldsm.trans row within k16
    const int vch = (lane >> 4) << 3;                          // ldsm.trans col offset
    const int g = lane >> 2, tg = lane & 3;
    const int wq0 = wid << 4;

    // prologue: Q (hi+lo), K tile 0 (hi+lo), V tile 0 — all cp.async, one group
    {
        #pragma unroll
        for (int j = 0; j < 4; j++) {
            int ch = tid + (j << 8);
            int row = ch >> 3, cc = ch & 7;
            uint32_t so = row * 144 + cc * 16;
            size_t ga = (tok0 + q0 + row) * D + hc + cc * 8;
            CP_ASYNC16(sb + AQ_H + so, Qh + ga);
            CP_ASYNC16(sb + AQ_L + so, Ql + ga);
        }
        #pragma unroll
        for (int j = 0; j < 2; j++) {
            int ch = tid + (j << 8);
            int row = ch >> 3, cc = ch & 7;
            uint32_t so = row * 144 + cc * 16;
            size_t ga = (tok0 + row) * KVD + hc + cc * 8;
            CP_ASYNC16(sb + AK_B(0) + so, Kh + ga);
            CP_ASYNC16(sb + AK_B(0) + 9216 + so, Kl + ga);
            CP_ASYNC16(sb + AV_B(0) + so, Vb + ga);
        }
        CP_COMMIT();
    }

    float o[8][4];
    #pragma unroll
    for (int j = 0; j < 8; j++)
        #pragma unroll
        for (int q = 0; q < 4; q++) o[j][q] = 0.f;
    float m0r = -1e30f, m1r = -1e30f, l0r = 0.f, l1r = 0.f;

    for (int kt = 0; kt < SEQL / 64; kt++) {
        const int s = kt & 1;
        if (kt + 1 < SEQL / 64) {
            const size_t kb = tok0 + (size_t)(kt + 1) * 64;
            #pragma unroll
            for (int j = 0; j < 2; j++) {
                int ch = tid + (j << 8);
                int row = ch >> 3, cc = ch & 7;
                uint32_t so = row * 144 + cc * 16;
                size_t ga = (kb + row) * KVD + hc + cc * 8;
                CP_ASYNC16(sb + AK_B(1 - s) + so, Kh + ga);
                CP_ASYNC16(sb + AK_B(1 - s) + 9216 + so, Kl + ga);
                CP_ASYNC16(sb + AV_B(1 - s) + so, Vb + ga);
            }
            CP_COMMIT();
            CP_WAIT1();
        } else {
            CP_WAIT0();
        }
        __syncthreads();

        // S = Q @ K^T (split-bf16 3-term)
        float sc[8][4];
        #pragma unroll
        for (int j = 0; j < 8; j++)
            #pragma unroll
            for (int q = 0; q < 4; q++) sc[j][q] = 0.f;
        #pragma unroll
        for (int kc = 0; kc < 4; kc++) {
            uint32_t ah[4], al[4];
            uint32_t ao = sb + (wq0 + arow) * 144 + ((kc << 4) + ak) * 2;
            ldsm4(ao + AQ_H, ah[0], ah[1], ah[2], ah[3]);
            ldsm4(ao + AQ_L, al[0], al[1], al[2], al[3]);
            #pragma unroll
            for (int jj = 0; jj < 4; jj++) {
                uint32_t bo = sb + AK_B(s) + ((jj << 4) + brow) * 144 + ((kc << 4) + bk) * 2;
                uint32_t bh0, bh1, bh2, bh3, bl0, bl1, bl2, bl3;
                ldsm4(bo, bh0, bh1, bh2, bh3);
                ldsm4(bo + 9216, bl0, bl1, bl2, bl3);
                mma_bf16(sc[2 * jj],     ah, bh0, bh1);
                mma_bf16(sc[2 * jj],     ah, bl0, bl1);
                mma_bf16(sc[2 * jj],     al, bh0, bh1);
                mma_bf16(sc[2 * jj + 1], ah, bh2, bh3);
                mma_bf16(sc[2 * jj + 1], ah, bl2, bl3);
                mma_bf16(sc[2 * jj + 1], al, bh2, bh3);
            }
        }
        // online softmax
        float mx0 = -1e30f, mx1 = -1e30f;
        #pragma unroll
        for (int j = 0; j < 8; j++) {
            sc[j][0] *= ATT_SCALE; sc[j][1] *= ATT_SCALE;
            sc[j][2] *= ATT_SCALE; sc[j][3] *= ATT_SCALE;
            mx0 = fmaxf(mx0, fmaxf(sc[j][0], sc[j][1]));
            mx1 = fmaxf(mx1, fmaxf(sc[j][2], sc[j][3]));
        }
        mx0 = fmaxf(mx0, __shfl_xor_sync(0xffffffffu, mx0, 1));
        mx0 = fmaxf(mx0, __shfl_xor_sync(0xffffffffu, mx0, 2));
        mx1 = fmaxf(mx1, __shfl_xor_sync(0xffffffffu, mx1, 1));
        mx1 = fmaxf(mx1, __shfl_xor_sync(0xffffffffu, mx1, 2));
        float mn0 = fmaxf(m0r, mx0), mn1 = fmaxf(m1r, mx1);
        float a0 = __expf(m0r - mn0), a1 = __expf(m1r - mn1);
        m0r = mn0; m1r = mn1;
        float rs0 = 0.f, rs1 = 0.f;
        #pragma unroll
        for (int j = 0; j < 8; j++) {
            sc[j][0] = __expf(sc[j][0] - mn0); sc[j][1] = __expf(sc[j][1] - mn0);
            sc[j][2] = __expf(sc[j][2] - mn1); sc[j][3] = __expf(sc[j][3] - mn1);
            rs0 += sc[j][0] + sc[j][1];
            rs1 += sc[j][2] + sc[j][3];
        }
        rs0 += __shfl_xor_sync(0xffffffffu, rs0, 1);
        rs0 += __shfl_xor_sync(0xffffffffu, rs0, 2);
        rs1 += __shfl_xor_sync(0xffffffffu, rs1, 1);
        rs1 += __shfl_xor_sync(0xffffffffu, rs1, 2);
        l0r = l0r * a0 + rs0;
        l1r = l1r * a1 + rs1;
        #pragma unroll
        for (int j = 0; j < 8; j++) {
            o[j][0] *= a0; o[j][1] *= a0; o[j][2] *= a1; o[j][3] *= a1;
        }
        // O += P @ V  (V row-major in smem; B frags via ldsm.trans)
        #pragma unroll
        for (int kk = 0; kk < 4; kk++) {
            uint32_t pa[4];
            __nv_bfloat162 t0 = __float22bfloat162_rn(make_float2(sc[2 * kk][0], sc[2 * kk][1]));
            __nv_bfloat162 t1 = __float22bfloat162_rn(make_float2(sc[2 * kk][2], sc[2 * kk][3]));
            __nv_bfloat162 t2 = __float22bfloat162_rn(make_float2(sc[2 * kk + 1][0], sc[2 * kk + 1][1]));
            __nv_bfloat162 t3 = __float22bfloat162_rn(make_float2(sc[2 * kk + 1][2], sc[2 * kk + 1][3]));
            pa[0] = *(uint32_t*)&t0; pa[1] = *(uint32_t*)&t1;
            pa[2] = *(uint32_t*)&t2; pa[3] = *(uint32_t*)&t3;
            #pragma unroll
            for (int jj = 0; jj < 4; jj++) {
                uint32_t bo = sb + AV_B(s) + ((kk << 4) + vrow) * 144 + ((jj << 4) + vch) * 2;
                uint32_t b0, b1, b2, b3;
                ldsm4t(bo, b0, b1, b2, b3);
                mma_bf16(o[2 * jj],     pa, b0, b1);
                mma_bf16(o[2 * jj + 1], pa, b2, b3);
            }
        }
        __syncthreads();
    }
    const float inv0 = 1.0f / l0r, inv1 = 1.0f / l1r;
    #pragma unroll
    for (int j = 0; j < 8; j++) {
        int col = hc + (j << 3) + (tg << 1);
        size_t r0 = (tok0 + q0 + wq0 + g) * D + col;
        size_t r1 = (tok0 + q0 + wq0 + g + 8) * D + col;
        uint32_t h0, l0, h1, l1;
        splitf2(o[j][0] * inv0, o[j][1] * inv0, h0, l0);
        splitf2(o[j][2] * inv1, o[j][3] * inv1, h1, l1);
        *(uint32_t*)(Oh + r0) = h0; *(uint32_t*)(Ol + r0) = l0;
        *(uint32_t*)(Oh + r1) = h1; *(uint32_t*)(Ol + r1) = l1;
    }
}

// -------------------- LN(a + resid)*g + be; resid fp32 or split bf16 -------------
__global__ __launch_bounds__(128) void ln_kernel(
    float* __restrict__ out, bf16* __restrict__ outH, bf16* __restrict__ outL,
    const float* __restrict__ a, const float* __restrict__ b,
    const bf16* __restrict__ bH, const bf16* __restrict__ bL,
    const float* __restrict__ g, const float* __restrict__ be,
    float* __restrict__ hn_out, int do_hn)
{
    __shared__ float sh[8];
    const int row = blockIdx.x, t = threadIdx.x;
    float4 av = *(const float4*)(a + (size_t)row * D + t * 4);
    float bvv[4];
    if (b) {
        float4 bv = *(const float4*)(b + (size_t)row * D + t * 4);
        bvv[0] = bv.x; bvv[1] = bv.y; bvv[2] = bv.z; bvv[3] = bv.w;
    } else {
        uint2 hv = *(const uint2*)(bH + (size_t)row * D + t * 4);
        uint2 lv = *(const uint2*)(bL + (size_t)row * D + t * 4);
        float2 h0 = __bfloat1622float2(*(__nv_bfloat162*)&hv.x);
        float2 h1 = __bfloat1622float2(*(__nv_bfloat162*)&hv.y);
        float2 l0 = __bfloat1622float2(*(__nv_bfloat162*)&lv.x);
        float2 l1 = __bfloat1622float2(*(__nv_bfloat162*)&lv.y);
        bvv[0] = h0.x + l0.x; bvv[1] = h0.y + l0.y;
        bvv[2] = h1.x + l1.x; bvv[3] = h1.y + l1.y;
    }
    float v[4] = {av.x + bvv[0], av.y + bvv[1], av.z + bvv[2], av.w + bvv[3]};
    float s = v[0] + v[1] + v[2] + v[3];
    float s2 = v[0] * v[0] + v[1] * v[1] + v[2] * v[2] + v[3] * v[3];
    #pragma unroll
    for (int off = 16; off; off >>= 1) {
        s += __shfl_xor_sync(0xffffffffu, s, off);
        s2 += __shfl_xor_sync(0xffffffffu, s2, off);
    }
    if ((t & 31) == 0) { sh[t >> 5] = s; sh[4 + (t >> 5)] = s2; }
    __syncthreads();
    s = sh[0] + sh[1] + sh[2] + sh[3];
    s2 = sh[4] + sh[5] + sh[6] + sh[7];
    const float mean = s * (1.0f / D);
    const float rstd = rsqrtf(s2 * (1.0f / D) - mean * mean + 1e-5f);
    float4 gv = *(const float4*)(g + t * 4);
    float4 bev = *(const float4*)(be + t * 4);
    float y[4];
    y[0] = (v[0] - mean) * rstd * gv.x + bev.x;
    y[1] = (v[1] - mean) * rstd * gv.y + bev.y;
    y[2] = (v[2] - mean) * rstd * gv.z + bev.z;
    y[3] = (v[3] - mean) * rstd * gv.w + bev.w;
    if (out)
        *(float4*)(out + (size_t)row * D + t * 4) = make_float4(y[0], y[1], y[2], y[3]);
    if (outH) {
        uint32_t h0, l0, h1, l1;
        splitf2(y[0], y[1], h0, l0);
        splitf2(y[2], y[3], h1, l1);
        *(uint2*)(outH + (size_t)row * D + t * 4) = make_uint2(h0, h1);
        *(uint2*)(outL + (size_t)row * D + t * 4) = make_uint2(l0, l1);
    }
    if (do_hn && (row & (SEQL - 1)) == SEQL - 1)
        *(float4*)(hn_out + (size_t)(row >> 10) * D + t * 4) = av;
}

// -------------------- launch --------------------
extern "C" void kernel_launch(void* const* d_in, const int* in_sizes, int n_in,
                              void* d_out, int out_size)
{
    const float* input   = (const float*)d_in[0];
    const float* wq_c    = (const float*)d_in[3];
    const float* fc_c    = (const float*)d_in[5];
    const float* wq_g    = (const float*)d_in[6];
    const float* wk_g    = (const float*)d_in[7];
    const float* fc_g    = (const float*)d_in[8];
    const float* wq_x    = (const float*)d_in[9];
    const float* fc_x    = (const float*)d_in[11];
    const float* conv1_w = (const float*)d_in[12];
    const float* conv2_w = (const float*)d_in[13];
    const float* ln1_g = (const float*)d_in[14];
    const float* ln1_b = (const float*)d_in[15];
    const float* ln2_g = (const float*)d_in[16];
    const float* ln2_b = (const float*)d_in[17];
    const float* ln3_g = (const float*)d_in[18];
    const float* ln3_b = (const float*)d_in[19];
    const float* ln4_g = (const float*)d_in[20];
    const float* ln4_b = (const float*)d_in[21];
    const float* mlp_w1 = (const float*)d_in[22];
    const float* mlp_b1 = (const float*)d_in[23];
    const float* mlp_w2 = (const float*)d_in[24];
    const float* mlp_b2 = (const float*)d_in[25];

    float *M1, *M3, *B0, *B1;
    bf16 *Wh, *Wl, *XH, *XL, *KVH, *KVL, *QH, *QL;
    bf16 *ATH, *ATL, *X1H, *X1L, *X2H, *X2L, *X3H, *X3L, *HIDH, *HIDL;
    cudaGetSymbolAddress((void**)&M1, d_M1);
    cudaGetSymbolAddress((void**)&M3, d_M3);
    cudaGetSymbolAddress((void**)&B0, d_B0);
    cudaGetSymbolAddress((void**)&B1, d_B1);
    cudaGetSymbolAddress((void**)&Wh, d_Wh);
    cudaGetSymbolAddress((void**)&Wl, d_Wl);
    cudaGetSymbolAddress((void**)&XH, d_XH);
    cudaGetSymbolAddress((void**)&XL, d_XL);
    cudaGetSymbolAddress((void**)&KVH, d_KVH);
    cudaGetSymbolAddress((void**)&KVL, d_KVL);
    cudaGetSymbolAddress((void**)&QH, d_QH);
    cudaGetSymbolAddress((void**)&QL, d_QL);
    cudaGetSymbolAddress((void**)&ATH, d_ATH);
    cudaGetSymbolAddress((void**)&ATL, d_ATL);
    cudaGetSymbolAddress((void**)&X1H, d_X1H);
    cudaGetSymbolAddress((void**)&X1L, d_X1L);
    cudaGetSymbolAddress((void**)&X2H, d_X2H);
    cudaGetSymbolAddress((void**)&X2L, d_X2L);
    cudaGetSymbolAddress((void**)&X3H, d_X3H);
    cudaGetSymbolAddress((void**)&X3L, d_X3L);
    cudaGetSymbolAddress((void**)&HIDH, d_HIDH);
    cudaGetSymbolAddress((void**)&HIDL, d_HIDL);

    cudaFuncSetAttribute(mma_gemm, cudaFuncAttributeMaxDynamicSharedMemorySize, TCG_SMEM);
    cudaFuncSetAttribute(attn_mma, cudaFuncAttributeMaxDynamicSharedMemorySize, AT_SMEM);

    float* outp = (float*)d_out;
    const size_t out_main = (size_t)N_TOK * D;
    float* hnp = outp + out_main;
    int do_hn = (out_size >= (int)(out_main + BSZ * D)) ? 1 : 0;
    if (!do_hn) hnp = outp;

    const dim3 blk(256);
    const dim3 tg512(D / 128, N_TOK / 128);       // (4, 128)
    const dim3 tg1536(12, N_TOK / 128);           // merged KV|u
    const dim3 tg2048(DFF / 128, N_TOK / 128);    // (16, 128)
    const dim3 gW(D / 64, D / 64);
    const int nW512 = D * D / 1024;
    const int nW2048 = D * DFF / 1024;
    const int nX = N_TOK * D / 1024;

    // ---- prep ----
    gemm_nn<<<gW, blk>>>(M1, fc_c, wq_c, D, D, D);
    gemm_nn<<<gW, blk>>>(M3, fc_x, wq_x, D, D, D);
    split_w<<<nW512, blk>>>(Wh + OFF_WKG, Wl + OFF_WKG, wk_g, D * D);
    split_w<<<nW512, blk>>>(Wh + OFF_WQG, Wl + OFF_WQG, wq_g, D * D);
    split_w<<<nX, blk>>>(XH, XL, input, N_TOK * D);
    fold_split<<<D, 128>>>(Wh + OFF_M1, Wl + OFF_M1, M1, conv1_w);
    fold_split<<<D, 128>>>(Wh + OFF_WQG2, Wl + OFF_WQG2, wq_g, conv2_w);
    split_w<<<nW512, blk>>>(Wh + OFF_FCG, Wl + OFF_FCG, fc_g, D * D);
    split_w<<<nW512, blk>>>(Wh + OFF_M3, Wl + OFF_M3, M3, D * D);
    split_w<<<nW2048, blk>>>(Wh + OFF_W1, Wl + OFF_W1, mlp_w1, D * DFF);
    split_w<<<nW2048, blk>>>(Wh + OFF_W2, Wl + OFF_W2, mlp_w2, D * DFF);

    // ---- merged: KV[:,0:1024] = X@[wkg;wqg]^T (split out), u = X@M1c^T (fp32 B1)
    mma_gemm<<<tg1536, blk, TCG_SMEM>>>(B1, KVH, KVL, XH, XL,
                                        Wh + OFF_WKG, Wl + OFF_WKG, N_TOK, 1536, D, nullptr, 0, 1);

    // ---- x1 = LN1(u + input)
    ln_kernel<<<N_TOK, 128>>>(nullptr, X1H, X1L, B1, input, nullptr, nullptr, ln1_g, ln1_b, hnp, 0);

    // ---- Q = x1 @ Wqg2^T (conv2 folded); attention; g = att @ fc_g^T; x2 = LN2(g + x1)
    mma_gemm<<<tg512, blk, TCG_SMEM>>>(nullptr, QH, QL, X1H, X1L,
                                       Wh + OFF_WQG2, Wl + OFF_WQG2, N_TOK, D, D, nullptr, 0, 0);
    attn_mma<<<dim3(SEQL / 128, 8, BSZ), blk, AT_SMEM>>>(ATH, ATL, QH, QL, KVH, KVL, KVH + 512);
    mma_gemm<<<tg512, blk, TCG_SMEM>>>(B0, nullptr, nullptr, ATH, ATL,
                                       Wh + OFF_FCG, Wl + OFF_FCG, N_TOK, D, D, nullptr, 0, 0);
    ln_kernel<<<N_TOK, 128>>>(nullptr, X2H, X2L, B0, nullptr, X1H, X1L, ln2_g, ln2_b, hnp, 0);

    // ---- h = x2 @ M3^T; x3 = LN3(h + x2); hn = raw h of last token
    mma_gemm<<<tg512, blk, TCG_SMEM>>>(B1, nullptr, nullptr, X2H, X2L,
                                       Wh + OFF_M3, Wl + OFF_M3, N_TOK, D, D, nullptr, 0, 0);
    ln_kernel<<<N_TOK, 128>>>(nullptr, X3H, X3L, B1, nullptr, X2H, X2L, ln3_g, ln3_b, hnp, do_hn);

    // ---- MLP: hid = gelu(x3 @ w1^T + b1); y = hid @ w2^T + b2; out = LN4(y + x3)
    mma_gemm<<<tg2048, blk, TCG_SMEM>>>(nullptr, HIDH, HIDL, X3H, X3L,
                                        Wh + OFF_W1, Wl + OFF_W1, N_TOK, DFF, D, mlp_b1, 1, 0);
    mma_gemm<<<tg512, blk, TCG_SMEM>>>(B0, nullptr, nullptr, HIDH, HIDL,
                                       Wh + OFF_W2, Wl + OFF_W2, N_TOK, D, DFF, mlp_b2, 0, 0);
    ln_kernel<<<N_TOK, 128>>>(outp, nullptr, nullptr, B0, nullptr, X3H, X3L, ln4_g, ln4_b, hnp, 0);
}

// round 15
// speedup vs baseline: 1.1797x; 1.0340x over previous
#include <cuda_runtime.h>
#include <cuda_bf16.h>
#include <math.h>
#include <stdint.h>

#define N_TOK 16384
#define D 512
#define SEQL 1024
#define BSZ 16
#define DFF 2048
#define KVD 1024
#define ATT_SCALE 0.125f

typedef __nv_bfloat16 bf16;

// -------------------- fp32 scratch --------------------
__device__ float d_M1[D * D];
__device__ float d_M3[D * D];
__device__ float d_B0[(size_t)N_TOK * D];
__device__ float d_B1[(size_t)N_TOK * D];

// -------------------- split-bf16 weights (wkg|wqg|M1c contiguous for merged GEMM) --
#define OFF_WKG  0
#define OFF_WQG  262144
#define OFF_M1   524288
#define OFF_FCG  786432
#define OFF_M3   1048576
#define OFF_W1   1310720
#define OFF_W2   2359296
#define OFF_WQG2 3407872
#define W_TOTAL  3670016
__device__ bf16 d_Wh[W_TOTAL];
__device__ bf16 d_Wl[W_TOTAL];

// -------------------- split-bf16 activations --------------------
#define ACT_N ((size_t)N_TOK * D)
__device__ bf16 d_XH[ACT_N],   d_XL[ACT_N];
__device__ bf16 d_KVH[(size_t)N_TOK * KVD], d_KVL[(size_t)N_TOK * KVD];
__device__ bf16 d_QH[ACT_N],   d_QL[ACT_N];
__device__ bf16 d_ATH[ACT_N],  d_ATL[ACT_N];
__device__ bf16 d_X1H[ACT_N],  d_X1L[ACT_N];
__device__ bf16 d_X2H[ACT_N],  d_X2L[ACT_N];
__device__ bf16 d_X3H[ACT_N],  d_X3L[ACT_N];
__device__ bf16 d_HIDH[(size_t)N_TOK * DFF], d_HIDL[(size_t)N_TOK * DFF];

// ==================== helpers ====================
__device__ __forceinline__ uint32_t smem_u32(const void* p) {
    uint32_t a;
    asm("{ .reg .u64 t; cvta.to.shared.u64 t, %1; cvt.u32.u64 %0, t; }" : "=r"(a) : "l"(p));
    return a;
}
__device__ __forceinline__ void ldsm4(uint32_t addr, uint32_t& r0, uint32_t& r1, uint32_t& r2, uint32_t& r3) {
    asm volatile("ldmatrix.sync.aligned.m8n8.x4.shared.b16 {%0,%1,%2,%3}, [%4];"
                 : "=r"(r0), "=r"(r1), "=r"(r2), "=r"(r3) : "r"(addr));
}
__device__ __forceinline__ void ldsm4t(uint32_t addr, uint32_t& r0, uint32_t& r1, uint32_t& r2, uint32_t& r3) {
    asm volatile("ldmatrix.sync.aligned.m8n8.x4.trans.shared.b16 {%0,%1,%2,%3}, [%4];"
                 : "=r"(r0), "=r"(r1), "=r"(r2), "=r"(r3) : "r"(addr));
}
__device__ __forceinline__ void mma_bf16(float c[4], const uint32_t a[4], uint32_t b0, uint32_t b1) {
    asm volatile(
        "mma.sync.aligned.m16n8k16.row.col.f32.bf16.bf16.f32 "
        "{%0,%1,%2,%3}, {%4,%5,%6,%7}, {%8,%9}, {%0,%1,%2,%3};"
        : "+f"(c[0]), "+f"(c[1]), "+f"(c[2]), "+f"(c[3])
        : "r"(a[0]), "r"(a[1]), "r"(a[2]), "r"(a[3]), "r"(b0), "r"(b1));
}
__device__ __forceinline__ void splitf2(float x, float y, uint32_t& h, uint32_t& l) {
    __nv_bfloat162 hh = __float22bfloat162_rn(make_float2(x, y));
    float2 hf = __bfloat1622float2(hh);
    __nv_bfloat162 ll = __float22bfloat162_rn(make_float2(x - hf.x, y - hf.y));
    h = *(uint32_t*)&hh; l = *(uint32_t*)&ll;
}
__device__ __forceinline__ void split2(float4 v, uint2& hi, uint2& lo) {
    uint32_t h0, l0, h1, l1;
    splitf2(v.x, v.y, h0, l0);
    splitf2(v.z, v.w, h1, l1);
    hi = make_uint2(h0, h1);
    lo = make_uint2(l0, l1);
}
#define CP_ASYNC16(dst, src) asm volatile("cp.async.cg.shared.global [%0], [%1], 16;" :: "r"(dst), "l"(src) : "memory")
#define CP_COMMIT()          asm volatile("cp.async.commit_group;" ::: "memory")
#define CP_WAIT0()           asm volatile("cp.async.wait_group 0;" ::: "memory")
#define CP_WAIT1()           asm volatile("cp.async.wait_group 1;" ::: "memory")

// -------------------- multi-source fp32 -> bf16 hi/lo split --------------------
#define NJOBS 7
struct SplitJobs {
    const float* src[NJOBS];
    bf16* dh[NJOBS];
    bf16* dl[NJOBS];
    int n[NJOBS];
    int start[NJOBS + 1];   // block-index prefix
};
__global__ __launch_bounds__(256) void multi_split(SplitJobs J)
{
    int b = blockIdx.x;
    int j = 0;
    #pragma unroll
    for (int t = 0; t < NJOBS - 1; t++)
        if (b >= J.start[t + 1]) j = t + 1;
    int local = b - J.start[j];
    int i = (local * 256 + threadIdx.x) * 4;
    if (i < J.n[j]) {
        float4 v = *(const float4*)(J.src[j] + i);
        uint2 h, l; split2(v, h, l);
        *(uint2*)(J.dh[j] + i) = h;
        *(uint2*)(J.dl[j] + i) = l;
    }
}

// -------------------- fold 3-tap conv into weight columns (2 jobs via grid.z) ----
__global__ __launch_bounds__(128) void fold_split2(
    bf16* __restrict__ H0, bf16* __restrict__ L0, const float* __restrict__ W0, const float* __restrict__ w0c,
    bf16* __restrict__ H1, bf16* __restrict__ L1, const float* __restrict__ W1p, const float* __restrict__ w1c)
{
    __shared__ float rb[D];
    const int row = blockIdx.x, t = threadIdx.x;
    const float* W = blockIdx.z ? W1p : W0;
    const float* w = blockIdx.z ? w1c : w0c;
    bf16* H = blockIdx.z ? H1 : H0;
    bf16* L = blockIdx.z ? L1 : L0;
    float4 v = *(const float4*)(W + (size_t)row * D + t * 4);
    *(float4*)&rb[t * 4] = v;
    __syncthreads();
    const float w0 = w[0], w1 = w[1], w2 = w[2];
    float y[4];
    #pragma unroll
    for (int i = 0; i < 4; i++) {
        int c = t * 4 + i;
        float xm = (c > 0) ? rb[c - 1] : 0.f;
        float xp = (c < D - 1) ? rb[c + 1] : 0.f;
        y[i] = w2 * xm + w1 * rb[c] + w0 * xp;
    }
    uint32_t h0, l0, h1, l1;
    splitf2(y[0], y[1], h0, l0);
    splitf2(y[2], y[3], h1, l1);
    *(uint2*)(H + (size_t)row * D + t * 4) = make_uint2(h0, h1);
    *(uint2*)(L + (size_t)row * D + t * 4) = make_uint2(l0, l1);
}

// ==================== single-stage streamed split-bf16 mma GEMM, 2 CTAs/SM ========
#define T_AH 0
#define T_AL 18432
#define T_BH 36864
#define T_BL 55296
#define TCG_SMEM 73728

__global__ __launch_bounds__(256, 2) void mma_gemm(
    float* __restrict__ C, bf16* __restrict__ Ch, bf16* __restrict__ Cl,
    const bf16* __restrict__ Ah, const bf16* __restrict__ Al,
    const bf16* __restrict__ Bh, const bf16* __restrict__ Bl,
    int M, int Nt, int K, const float* __restrict__ bias, int act, int mode)
{
    extern __shared__ char smem[];
    const uint32_t sb = smem_u32(smem);
    const int tid = threadIdx.x, wid = tid >> 5, lane = tid & 31;
    const int m0 = blockIdx.y * 128, n0 = blockIdx.x * 128;
    const int wm = (wid & 3) << 5;
    const int wn = (wid >> 2) << 6;
    const int quad = lane >> 3, r = lane & 7;
    const int arow = ((quad & 1) << 3) + r, ak = (quad >> 1) << 3;
    const int brow = ((quad >> 1) << 3) + r, bk = (quad & 1) << 3;

    float acc[2][8][4];
    #pragma unroll
    for (int i = 0; i < 2; i++)
        #pragma unroll
        for (int j = 0; j < 8; j++)
            #pragma unroll
            for (int q = 0; q < 4; q++) acc[i][j][q] = 0.f;

    const int nit = K >> 6;

    #pragma unroll
    for (int j = 0; j < 4; j++) {
        int ch = tid + (j << 8);
        int row = ch >> 3, cc = ch & 7;
        uint32_t so = row * 144 + cc * 16;
        size_t ga = (size_t)(m0 + row) * K + cc * 8;
        size_t gb = (size_t)(n0 + row) * K + cc * 8;
        CP_ASYNC16(sb + T_AH + so, Ah + ga);
        CP_ASYNC16(sb + T_AL + so, Al + ga);
        CP_ASYNC16(sb + T_BH + so, Bh + gb);
        CP_ASYNC16(sb + T_BL + so, Bl + gb);
    }
    CP_COMMIT();

    for (int it = 0; it < nit; it++) {
        CP_WAIT0();
        __syncthreads();
        #pragma unroll
        for (int kc = 0; kc < 4; kc++) {
            uint32_t ah[2][4], al[2][4];
            #pragma unroll
            for (int i = 0; i < 2; i++) {
                uint32_t ao = sb + (wm + (i << 4) + arow) * 144 + ((kc << 4) + ak) * 2;
                ldsm4(ao + T_AH, ah[i][0], ah[i][1], ah[i][2], ah[i][3]);
                ldsm4(ao + T_AL, al[i][0], al[i][1], al[i][2], al[i][3]);
            }
            #pragma unroll
            for (int jj = 0; jj < 4; jj++) {
                uint32_t bo = sb + (wn + (jj << 4) + brow) * 144 + ((kc << 4) + bk) * 2;
                uint32_t bh0, bh1, bh2, bh3, bl0, bl1, bl2, bl3;
                ldsm4(bo + T_BH, bh0, bh1, bh2, bh3);
                ldsm4(bo + T_BL, bl0, bl1, bl2, bl3);
                #pragma unroll
                for (int i = 0; i < 2; i++) {
                    mma_bf16(acc[i][2 * jj],     ah[i], bh0, bh1);
                    mma_bf16(acc[i][2 * jj],     ah[i], bl0, bl1);
                    mma_bf16(acc[i][2 * jj],     al[i], bh0, bh1);
                    mma_bf16(acc[i][2 * jj + 1], ah[i], bh2, bh3);
                    mma_bf16(acc[i][2 * jj + 1], ah[i], bl2, bl3);
                    mma_bf16(acc[i][2 * jj + 1], al[i], bh2, bh3);
                }
            }
        }
        __syncthreads();
        if (it + 1 < nit) {
            const int k0 = (it + 1) << 6;
            #pragma unroll
            for (int j = 0; j < 4; j++) {
                int ch = tid + (j << 8);
                int row = ch >> 3, cc = ch & 7;
                uint32_t so = row * 144 + cc * 16;
                size_t ga = (size_t)(m0 + row) * K + k0 + cc * 8;
                size_t gb = (size_t)(n0 + row) * K + k0 + cc * 8;
                CP_ASYNC16(sb + T_AH + so, Ah + ga);
                CP_ASYNC16(sb + T_AL + so, Al + ga);
                CP_ASYNC16(sb + T_BH + so, Bh + gb);
                CP_ASYNC16(sb + T_BL + so, Bl + gb);
            }
            CP_COMMIT();
        }
    }

    const int g = lane >> 2, tg = (lane & 3) << 1;
    #pragma unroll
    for (int i = 0; i < 2; i++) {
        const int row0 = m0 + wm + (i << 4) + g;
        #pragma unroll
        for (int j = 0; j < 8; j++) {
            const int col = n0 + wn + (j << 3) + tg;
            float v0 = acc[i][j][0], v1 = acc[i][j][1];
            float v2 = acc[i][j][2], v3 = acc[i][j][3];
            if (mode == 1) {
                if (col < KVD) {
                    uint32_t h0, l0, h1, l1;
                    splitf2(v0, v1, h0, l0);
                    splitf2(v2, v3, h1, l1);
                    *(uint32_t*)(Ch + (size_t)row0 * KVD + col) = h0;
                    *(uint32_t*)(Ch + (size_t)(row0 + 8) * KVD + col) = h1;
                    *(uint32_t*)(Cl + (size_t)row0 * KVD + col) = l0;
                    *(uint32_t*)(Cl + (size_t)(row0 + 8) * KVD + col) = l1;
                } else {
                    *(float2*)(C + (size_t)row0 * D + col - KVD) = make_float2(v0, v1);
                    *(float2*)(C + (size_t)(row0 + 8) * D + col - KVD) = make_float2(v2, v3);
                }
                continue;
            }
            float b0 = 0.f, b1 = 0.f;
            if (bias) { b0 = bias[col]; b1 = bias[col + 1]; }
            v0 += b0; v1 += b1; v2 += b0; v3 += b1;
            if (act) {
                v0 = 0.5f * v0 * (1.0f + erff(v0 * 0.70710678118654752f));
                v1 = 0.5f * v1 * (1.0f + erff(v1 * 0.70710678118654752f));
                v2 = 0.5f * v2 * (1.0f + erff(v2 * 0.70710678118654752f));
                v3 = 0.5f * v3 * (1.0f + erff(v3 * 0.70710678118654752f));
            }
            if (C) {
                *(float2*)(C + (size_t)row0 * Nt + col) = make_float2(v0, v1);
                *(float2*)(C + (size_t)(row0 + 8) * Nt + col) = make_float2(v2, v3);
            }
            if (Ch) {
                uint32_t h0, l0, h1, l1;
                splitf2(v0, v1, h0, l0);
                splitf2(v2, v3, h1, l1);
                *(uint32_t*)(Ch + (size_t)row0 * Nt + col) = h0;
                *(uint32_t*)(Ch + (size_t)(row0 + 8) * Nt + col) = h1;
                if (Cl) {
                    *(uint32_t*)(Cl + (size_t)row0 * Nt + col) = l0;
                    *(uint32_t*)(Cl + (size_t)(row0 + 8) * Nt + col) = l1;
                }
            }
        }
    }
}

// -------------------- GEMM NN (fp32, weight folding; grid.z selects job) ----------
__global__ __launch_bounds__(256) void gemm_nn2(
    float* __restrict__ C0, const float* __restrict__ A0, const float* __restrict__ B0p,
    float* __restrict__ C1, const float* __restrict__ A1, const float* __restrict__ B1p,
    int M, int N, int K)
{
    float* C = blockIdx.z ? C1 : C0;
    const float* A = blockIdx.z ? A1 : A0;
    const float* B = blockIdx.z ? B1p : B0p;
    __shared__ float As[16][64];
    __shared__ float Bs[16][64];
    const int tid = threadIdx.x;
    const int tx = tid & 15, ty = tid >> 4;
    const int lr = tid >> 2, lc = (tid & 3) << 2;
    const int bkr = tid >> 4, bnc = (tid & 15) << 2;
    const float* Ab = A + (size_t)blockIdx.y * 64 * K;
    float acc[4][4] = {};
    for (int k0 = 0; k0 < K; k0 += 16) {
        float4 a4 = *(const float4*)(Ab + (size_t)lr * K + k0 + lc);
        float4 b4 = *(const float4*)(B + (size_t)(k0 + bkr) * N + blockIdx.x * 64 + bnc);
        __syncthreads();
        As[lc + 0][lr] = a4.x; As[lc + 1][lr] = a4.y; As[lc + 2][lr] = a4.z; As[lc + 3][lr] = a4.w;
        *(float4*)&Bs[bkr][bnc] = b4;
        __syncthreads();
        #pragma unroll
        for (int k = 0; k < 16; k++) {
            float4 av = *(const float4*)&As[k][ty << 2];
            float4 bv = *(const float4*)&Bs[k][tx << 2];
            float a[4] = {av.x, av.y, av.z, av.w};
            float b[4] = {bv.x, bv.y, bv.z, bv.w};
            #pragma unroll
            for (int i = 0; i < 4; i++)
                #pragma unroll
                for (int j = 0; j < 4; j++) acc[i][j] += a[i] * b[j];
        }
    }
    #pragma unroll
    for (int i = 0; i < 4; i++) {
        int m = blockIdx.y * 64 + (ty << 2) + i;
        #pragma unroll
        for (int j = 0; j < 4; j++)
            C[(size_t)m * N + blockIdx.x * 64 + (tx << 2) + j] = acc[i][j];
    }
}

// ==================== tensor-core flash attention ====================
#define AQ_H 0
#define AQ_L 18432
#define AK_B(s) (36864 + (s) * 18432)
#define AV_B(s) (73728 + (s) * 9216)
#define AT_SMEM 92160

__global__ __launch_bounds__(256, 1) void attn_mma(
    bf16* __restrict__ Oh, bf16* __restrict__ Ol,
    const bf16* __restrict__ Qh, const bf16* __restrict__ Ql,
    const bf16* __restrict__ Kh, const bf16* __restrict__ Kl,
    const bf16* __restrict__ Vb)
{
    extern __shared__ char smem[];
    const uint32_t sb = smem_u32(smem);
    const int tid = threadIdx.x, wid = tid >> 5, lane = tid & 31;
    const int b = blockIdx.z, h = blockIdx.y;
    const int q0 = blockIdx.x * 128;
    const size_t tok0 = (size_t)b * SEQL;
    const int hc = h * 64;
    const int quad = lane >> 3, r = lane & 7;
    const int arow = ((quad & 1) << 3) + r, ak = (quad >> 1) << 3;
    const int brow = ((quad >> 1) << 3) + r, bk = (quad & 1) << 3;
    const int vrow = (((lane >> 3) & 1) << 3) + (lane & 7);
    const int vch = (lane >> 4) << 3;
    const int g = lane >> 2, tg = lane & 3;
    const int wq0 = wid << 4;

    {
        #pragma unroll
        for (int j = 0; j < 4; j++) {
            int ch = tid + (j << 8);
            int row = ch >> 3, cc = ch & 7;
            uint32_t so = row * 144 + cc * 16;
            size_t ga = (tok0 + q0 + row) * D + hc + cc * 8;
            CP_ASYNC16(sb + AQ_H + so, Qh + ga);
            CP_ASYNC16(sb + AQ_L + so, Ql + ga);
        }
        #pragma unroll
        for (int j = 0; j < 2; j++) {
            int ch = tid + (j << 8);
            int row = ch >> 3, cc = ch & 7;
            uint32_t so = row * 144 + cc * 16;
            size_t ga = (tok0 + row) * KVD + hc + cc * 8;
            CP_ASYNC16(sb + AK_B(0) + so, Kh + ga);
            CP_ASYNC16(sb + AK_B(0) + 9216 + so, Kl + ga);
            CP_ASYNC16(sb + AV_B(0) + so, Vb + ga);
        }
        CP_COMMIT();
    }

    float o[8][4];
    #pragma unroll
    for (int j = 0; j < 8; j++)
        #pragma unroll
        for (int q = 0; q < 4; q++) o[j][q] = 0.f;
    float m0r = -1e30f, m1r = -1e30f, l0r = 0.f, l1r = 0.f;

    for (int kt = 0; kt < SEQL / 64; kt++) {
        const int s = kt & 1;
        if (kt + 1 < SEQL / 64) {
            const size_t kb = tok0 + (size_t)(kt + 1) * 64;
            #pragma unroll
            for (int j = 0; j < 2; j++) {
                int ch = tid + (j << 8);
                int row = ch >> 3, cc = ch & 7;
                uint32_t so = row * 144 + cc * 16;
                size_t ga = (kb + row) * KVD + hc + cc * 8;
                CP_ASYNC16(sb + AK_B(1 - s) + so, Kh + ga);
                CP_ASYNC16(sb + AK_B(1 - s) + 9216 + so, Kl + ga);
                CP_ASYNC16(sb + AV_B(1 - s) + so, Vb + ga);
            }
            CP_COMMIT();
            CP_WAIT1();
        } else {
            CP_WAIT0();
        }
        __syncthreads();

        float sc[8][4];
        #pragma unroll
        for (int j = 0; j < 8; j++)
            #pragma unroll
            for (int q = 0; q < 4; q++) sc[j][q] = 0.f;
        #pragma unroll
        for (int kc = 0; kc < 4; kc++) {
            uint32_t ah[4], al[4];
            uint32_t ao = sb + (wq0 + arow) * 144 + ((kc << 4) + ak) * 2;
            ldsm4(ao + AQ_H, ah[0], ah[1], ah[2], ah[3]);
            ldsm4(ao + AQ_L, al[0], al[1], al[2], al[3]);
            #pragma unroll
            for (int jj = 0; jj < 4; jj++) {
                uint32_t bo = sb + AK_B(s) + ((jj << 4) + brow) * 144 + ((kc << 4) + bk) * 2;
                uint32_t bh0, bh1, bh2, bh3, bl0, bl1, bl2, bl3;
                ldsm4(bo, bh0, bh1, bh2, bh3);
                ldsm4(bo + 9216, bl0, bl1, bl2, bl3);
                mma_bf16(sc[2 * jj],     ah, bh0, bh1);
                mma_bf16(sc[2 * jj],     ah, bl0, bl1);
                mma_bf16(sc[2 * jj],     al, bh0, bh1);
                mma_bf16(sc[2 * jj + 1], ah, bh2, bh3);
                mma_bf16(sc[2 * jj + 1], ah, bl2, bl3);
                mma_bf16(sc[2 * jj + 1], al, bh2, bh3);
            }
        }
        float mx0 = -1e30f, mx1 = -1e30f;
        #pragma unroll
        for (int j = 0; j < 8; j++) {
            sc[j][0] *= ATT_SCALE; sc[j][1] *= ATT_SCALE;
            sc[j][2] *= ATT_SCALE; sc[j][3] *= ATT_SCALE;
            mx0 = fmaxf(mx0, fmaxf(sc[j][0], sc[j][1]));
            mx1 = fmaxf(mx1, fmaxf(sc[j][2], sc[j][3]));
        }
        mx0 = fmaxf(mx0, __shfl_xor_sync(0xffffffffu, mx0, 1));
        mx0 = fmaxf(mx0, __shfl_xor_sync(0xffffffffu, mx0, 2));
        mx1 = fmaxf(mx1, __shfl_xor_sync(0xffffffffu, mx1, 1));
        mx1 = fmaxf(mx1, __shfl_xor_sync(0xffffffffu, mx1, 2));
        float mn0 = fmaxf(m0r, mx0), mn1 = fmaxf(m1r, mx1);
        float a0 = __expf(m0r - mn0), a1 = __expf(m1r - mn1);
        m0r = mn0; m1r = mn1;
        float rs0 = 0.f, rs1 = 0.f;
        #pragma unroll
        for (int j = 0; j < 8; j++) {
            sc[j][0] = __expf(sc[j][0] - mn0); sc[j][1] = __expf(sc[j][1] - mn0);
            sc[j][2] = __expf(sc[j][2] - mn1); sc[j][3] = __expf(sc[j][3] - mn1);
            rs0 += sc[j][0] + sc[j][1];
            rs1 += sc[j][2] + sc[j][3];
        }
        rs0 += __shfl_xor_sync(0xffffffffu, rs0, 1);
        rs0 += __shfl_xor_sync(0xffffffffu, rs0, 2);
        rs1 += __shfl_xor_sync(0xffffffffu, rs1, 1);
        rs1 += __shfl_xor_sync(0xffffffffu, rs1, 2);
        l0r = l0r * a0 + rs0;
        l1r = l1r * a1 + rs1;
        #pragma unroll
        for (int j = 0; j < 8; j++) {
            o[j][0] *= a0; o[j][1] *= a0; o[j][2] *= a1; o[j][3] *= a1;
        }
        #pragma unroll
        for (int kk = 0; kk < 4; kk++) {
            uint32_t pa[4];
            __nv_bfloat162 t0 = __float22bfloat162_rn(make_float2(sc[2 * kk][0], sc[2 * kk][1]));
            __nv_bfloat162 t1 = __float22bfloat162_rn(make_float2(sc[2 * kk][2], sc[2 * kk][3]));
            __nv_bfloat162 t2 = __float22bfloat162_rn(make_float2(sc[2 * kk + 1][0], sc[2 * kk + 1][1]));
            __nv_bfloat162 t3 = __float22bfloat162_rn(make_float2(sc[2 * kk + 1][2], sc[2 * kk + 1][3]));
            pa[0] = *(uint32_t*)&t0; pa[1] = *(uint32_t*)&t1;
            pa[2] = *(uint32_t*)&t2; pa[3] = *(uint32_t*)&t3;
            #pragma unroll
            for (int jj = 0; jj < 4; jj++) {
                uint32_t bo = sb + AV_B(s) + ((kk << 4) + vrow) * 144 + ((jj << 4) + vch) * 2;
                uint32_t b0, b1, b2, b3;
                ldsm4t(bo, b0, b1, b2, b3);
                mma_bf16(o[2 * jj],     pa, b0, b1);
                mma_bf16(o[2 * jj + 1], pa, b2, b3);
            }
        }
        __syncthreads();
    }
    const float inv0 = 1.0f / l0r, inv1 = 1.0f / l1r;
    #pragma unroll
    for (int j = 0; j < 8; j++) {
        int col = hc + (j << 3) + (tg << 1);
        size_t r0 = (tok0 + q0 + wq0 + g) * D + col;
        size_t r1 = (tok0 + q0 + wq0 + g + 8) * D + col;
        uint32_t h0, l0, h1, l1;
        splitf2(o[j][0] * inv0, o[j][1] * inv0, h0, l0);
        splitf2(o[j][2] * inv1, o[j][3] * inv1, h1, l1);
        *(uint32_t*)(Oh + r0) = h0; *(uint32_t*)(Ol + r0) = l0;
        *(uint32_t*)(Oh + r1) = h1; *(uint32_t*)(Ol + r1) = l1;
    }
}

// -------------------- LN(a + resid)*g + be; resid fp32 or split bf16 -------------
__global__ __launch_bounds__(128) void ln_kernel(
    float* __restrict__ out, bf16* __restrict__ outH, bf16* __restrict__ outL,
    const float* __restrict__ a, const float* __restrict__ b,
    const bf16* __restrict__ bH, const bf16* __restrict__ bL,
    const float* __restrict__ g, const float* __restrict__ be,
    float* __restrict__ hn_out, int do_hn)
{
    __shared__ float sh[8];
    const int row = blockIdx.x, t = threadIdx.x;
    float4 av = *(const float4*)(a + (size_t)row * D + t * 4);
    float bvv[4];
    if (b) {
        float4 bv = *(const float4*)(b + (size_t)row * D + t * 4);
        bvv[0] = bv.x; bvv[1] = bv.y; bvv[2] = bv.z; bvv[3] = bv.w;
    } else {
        uint2 hv = *(const uint2*)(bH + (size_t)row * D + t * 4);
        uint2 lv = *(const uint2*)(bL + (size_t)row * D + t * 4);
        float2 h0 = __bfloat1622float2(*(__nv_bfloat162*)&hv.x);
        float2 h1 = __bfloat1622float2(*(__nv_bfloat162*)&hv.y);
        float2 l0 = __bfloat1622float2(*(__nv_bfloat162*)&lv.x);
        float2 l1 = __bfloat1622float2(*(__nv_bfloat162*)&lv.y);
        bvv[0] = h0.x + l0.x; bvv[1] = h0.y + l0.y;
        bvv[2] = h1.x + l1.x; bvv[3] = h1.y + l1.y;
    }
    float v[4] = {av.x + bvv[0], av.y + bvv[1], av.z + bvv[2], av.w + bvv[3]};
    float s = v[0] + v[1] + v[2] + v[3];
    float s2 = v[0] * v[0] + v[1] * v[1] + v[2] * v[2] + v[3] * v[3];
    #pragma unroll
    for (int off = 16; off; off >>= 1) {
        s += __shfl_xor_sync(0xffffffffu, s, off);
        s2 += __shfl_xor_sync(0xffffffffu, s2, off);
    }
    if ((t & 31) == 0) { sh[t >> 5] = s; sh[4 + (t >> 5)] = s2; }
    __syncthreads();
    s = sh[0] + sh[1] + sh[2] + sh[3];
    s2 = sh[4] + sh[5] + sh[6] + sh[7];
    const float mean = s * (1.0f / D);
    const float rstd = rsqrtf(s2 * (1.0f / D) - mean * mean + 1e-5f);
    float4 gv = *(const float4*)(g + t * 4);
    float4 bev = *(const float4*)(be + t * 4);
    float y[4];
    y[0] = (v[0] - mean) * rstd * gv.x + bev.x;
    y[1] = (v[1] - mean) * rstd * gv.y + bev.y;
    y[2] = (v[2] - mean) * rstd * gv.z + bev.z;
    y[3] = (v[3] - mean) * rstd * gv.w + bev.w;
    if (out)
        *(float4*)(out + (size_t)row * D + t * 4) = make_float4(y[0], y[1], y[2], y[3]);
    if (outH) {
        uint32_t h0, l0, h1, l1;
        splitf2(y[0], y[1], h0, l0);
        splitf2(y[2], y[3], h1, l1);
        *(uint2*)(outH + (size_t)row * D + t * 4) = make_uint2(h0, h1);
        *(uint2*)(outL + (size_t)row * D + t * 4) = make_uint2(l0, l1);
    }
    if (do_hn && (row & (SEQL - 1)) == SEQL - 1)
        *(float4*)(hn_out + (size_t)(row >> 10) * D + t * 4) = av;
}

// -------------------- launch --------------------
extern "C" void kernel_launch(void* const* d_in, const int* in_sizes, int n_in,
                              void* d_out, int out_size)
{
    const float* input   = (const float*)d_in[0];
    const float* wq_c    = (const float*)d_in[3];
    const float* fc_c    = (const float*)d_in[5];
    const float* wq_g    = (const float*)d_in[6];
    const float* wk_g    = (const float*)d_in[7];
    const float* fc_g    = (const float*)d_in[8];
    const float* wq_x    = (const float*)d_in[9];
    const float* fc_x    = (const float*)d_in[11];
    const float* conv1_w = (const float*)d_in[12];
    const float* conv2_w = (const float*)d_in[13];
    const float* ln1_g = (const float*)d_in[14];
    const float* ln1_b = (const float*)d_in[15];
    const float* ln2_g = (const float*)d_in[16];
    const float* ln2_b = (const float*)d_in[17];
    const float* ln3_g = (const float*)d_in[18];
    const float* ln3_b = (const float*)d_in[19];
    const float* ln4_g = (const float*)d_in[20];
    const float* ln4_b = (const float*)d_in[21];
    const float* mlp_w1 = (const float*)d_in[22];
    const float* mlp_b1 = (const float*)d_in[23];
    const float* mlp_w2 = (const float*)d_in[24];
    const float* mlp_b2 = (const float*)d_in[25];

    float *M1, *M3, *B0, *B1;
    bf16 *Wh, *Wl, *XH, *XL, *KVH, *KVL, *QH, *QL;
    bf16 *ATH, *ATL, *X1H, *X1L, *X2H, *X2L, *X3H, *X3L, *HIDH, *HIDL;
    cudaGetSymbolAddress((void**)&M1, d_M1);
    cudaGetSymbolAddress((void**)&M3, d_M3);
    cudaGetSymbolAddress((void**)&B0, d_B0);
    cudaGetSymbolAddress((void**)&B1, d_B1);
    cudaGetSymbolAddress((void**)&Wh, d_Wh);
    cudaGetSymbolAddress((void**)&Wl, d_Wl);
    cudaGetSymbolAddress((void**)&XH, d_XH);
    cudaGetSymbolAddress((void**)&XL, d_XL);
    cudaGetSymbolAddress((void**)&KVH, d_KVH);
    cudaGetSymbolAddress((void**)&KVL, d_KVL);
    cudaGetSymbolAddress((void**)&QH, d_QH);
    cudaGetSymbolAddress((void**)&QL, d_QL);
    cudaGetSymbolAddress((void**)&ATH, d_ATH);
    cudaGetSymbolAddress((void**)&ATL, d_ATL);
    cudaGetSymbolAddress((void**)&X1H, d_X1H);
    cudaGetSymbolAddress((void**)&X1L, d_X1L);
    cudaGetSymbolAddress((void**)&X2H, d_X2H);
    cudaGetSymbolAddress((void**)&X2L, d_X2L);
    cudaGetSymbolAddress((void**)&X3H, d_X3H);
    cudaGetSymbolAddress((void**)&X3L, d_X3L);
    cudaGetSymbolAddress((void**)&HIDH, d_HIDH);
    cudaGetSymbolAddress((void**)&HIDL, d_HIDL);

    cudaFuncSetAttribute(mma_gemm, cudaFuncAttributeMaxDynamicSharedMemorySize, TCG_SMEM);
    cudaFuncSetAttribute(attn_mma, cudaFuncAttributeMaxDynamicSharedMemorySize, AT_SMEM);

    float* outp = (float*)d_out;
    const size_t out_main = (size_t)N_TOK * D;
    float* hnp = outp + out_main;
    int do_hn = (out_size >= (int)(out_main + BSZ * D)) ? 1 : 0;
    if (!do_hn) hnp = outp;

    const dim3 blk(256);
    const dim3 tg512(D / 128, N_TOK / 128);
    const dim3 tg1536(12, N_TOK / 128);
    const dim3 tg2048(DFF / 128, N_TOK / 128);

    // ---- prep phase: 3 launches ----
    // 1) both weight foldings (M1 = fc_c@wq_c, M3 = fc_x@wq_x)
    gemm_nn2<<<dim3(D / 64, D / 64, 2), blk>>>(M1, fc_c, wq_c, M3, fc_x, wq_x, D, D, D);
    // 2) all plain splits in one launch
    {
        SplitJobs J;
        const float* srcs[NJOBS] = {wk_g, wq_g, fc_g, M3, mlp_w1, mlp_w2, input};
        bf16* dhs[NJOBS] = {Wh + OFF_WKG, Wh + OFF_WQG, Wh + OFF_FCG, Wh + OFF_M3,
                            Wh + OFF_W1, Wh + OFF_W2, XH};
        bf16* dls[NJOBS] = {Wl + OFF_WKG, Wl + OFF_WQG, Wl + OFF_FCG, Wl + OFF_M3,
                            Wl + OFF_W1, Wl + OFF_W2, XL};
        int ns[NJOBS] = {D * D, D * D, D * D, D * D, D * DFF, D * DFF, N_TOK * D};
        int total = 0;
        for (int j = 0; j < NJOBS; j++) {
            J.src[j] = srcs[j]; J.dh[j] = dhs[j]; J.dl[j] = dls[j]; J.n[j] = ns[j];
            J.start[j] = total;
            total += (ns[j] + 1023) / 1024;
        }
        J.start[NJOBS] = total;
        multi_split<<<total, blk>>>(J);
    }
    // 3) both conv foldings (conv1->M1, conv2->wq_g)
    fold_split2<<<dim3(D, 1, 2), 128>>>(Wh + OFF_M1, Wl + OFF_M1, M1, conv1_w,
                                        Wh + OFF_WQG2, Wl + OFF_WQG2, wq_g, conv2_w);

    // ---- merged: KV[:,0:1024] = X@[wkg;wqg]^T (split out), u = X@M1c^T (fp32 B1)
    mma_gemm<<<tg1536, blk, TCG_SMEM>>>(B1, KVH, KVL, XH, XL,
                                        Wh + OFF_WKG, Wl + OFF_WKG, N_TOK, 1536, D, nullptr, 0, 1);

    // ---- x1 = LN1(u + input)
    ln_kernel<<<N_TOK, 128>>>(nullptr, X1H, X1L, B1, input, nullptr, nullptr, ln1_g, ln1_b, hnp, 0);

    // ---- Q; attention; g; x2 = LN2(g + x1)
    mma_gemm<<<tg512, blk, TCG_SMEM>>>(nullptr, QH, QL, X1H, X1L,
                                       Wh + OFF_WQG2, Wl + OFF_WQG2, N_TOK, D, D, nullptr, 0, 0);
    attn_mma<<<dim3(SEQL / 128, 8, BSZ), blk, AT_SMEM>>>(ATH, ATL, QH, QL, KVH, KVL, KVH + 512);
    mma_gemm<<<tg512, blk, TCG_SMEM>>>(B0, nullptr, nullptr, ATH, ATL,
                                       Wh + OFF_FCG, Wl + OFF_FCG, N_TOK, D, D, nullptr, 0, 0);
    ln_kernel<<<N_TOK, 128>>>(nullptr, X2H, X2L, B0, nullptr, X1H, X1L, ln2_g, ln2_b, hnp, 0);

    // ---- h = x2 @ M3^T; x3 = LN3(h + x2); hn
    mma_gemm<<<tg512, blk, TCG_SMEM>>>(B1, nullptr, nullptr, X2H, X2L,
                                       Wh + OFF_M3, Wl + OFF_M3, N_TOK, D, D, nullptr, 0, 0);
    ln_kernel<<<N_TOK, 128>>>(nullptr, X3H, X3L, B1, nullptr, X2H, X2L, ln3_g, ln3_b, hnp, do_hn);

    // ---- MLP
    mma_gemm<<<tg2048, blk, TCG_SMEM>>>(nullptr, HIDH, HIDL, X3H, X3L,
                                        Wh + OFF_W1, Wl + OFF_W1, N_TOK, DFF, D, mlp_b1, 1, 0);
    mma_gemm<<<tg512, blk, TCG_SMEM>>>(B0, nullptr, nullptr, HIDH, HIDL,
                                       Wh + OFF_W2, Wl + OFF_W2, N_TOK, D, DFF, mlp_b2, 0, 0);
    ln_kernel<<<N_TOK, 128>>>(outp, nullptr, nullptr, B0, nullptr, X3H, X3L, ln4_g, ln4_b, hnp, 0);
}

// round 16
// speedup vs baseline: 1.1984x; 1.0159x over previous
#include <cuda_runtime.h>
#include <cuda_bf16.h>
#include <math.h>
#include <stdint.h>

#define N_TOK 16384
#define D 512
#define SEQL 1024
#define BSZ 16
#define DFF 2048
#define KVD 1024
#define ATT_SCALE 0.125f

typedef __nv_bfloat16 bf16;

// -------------------- fp32 scratch --------------------
__device__ float d_M1[D * D];
__device__ float d_M3[D * D];
__device__ float d_B0[(size_t)N_TOK * D];
__device__ float d_B1[(size_t)N_TOK * D];

// -------------------- split-bf16 weights --------------------
#define OFF_WKG  0
#define OFF_WQG  262144
#define OFF_M1   524288
#define OFF_FCG  786432
#define OFF_M3   1048576
#define OFF_W1   1310720
#define OFF_W2   2359296
#define OFF_WQG2 3407872
#define W_TOTAL  3670016
__device__ bf16 d_Wh[W_TOTAL];
__device__ bf16 d_Wl[W_TOTAL];

// -------------------- split-bf16 activations --------------------
#define ACT_N ((size_t)N_TOK * D)
__device__ bf16 d_XH[ACT_N],   d_XL[ACT_N];
__device__ bf16 d_KVH[(size_t)N_TOK * KVD], d_KVL[(size_t)N_TOK * KVD];
__device__ bf16 d_QH[ACT_N],   d_QL[ACT_N];
__device__ bf16 d_ATH[ACT_N],  d_ATL[ACT_N];
__device__ bf16 d_X1H[ACT_N],  d_X1L[ACT_N];
__device__ bf16 d_X2H[ACT_N],  d_X2L[ACT_N];
__device__ bf16 d_X3H[ACT_N],  d_X3L[ACT_N];
__device__ bf16 d_HIDH[(size_t)N_TOK * DFF], d_HIDL[(size_t)N_TOK * DFF];

// ==================== helpers ====================
__device__ __forceinline__ uint32_t smem_u32(const void* p) {
    uint32_t a;
    asm("{ .reg .u64 t; cvta.to.shared.u64 t, %1; cvt.u32.u64 %0, t; }" : "=r"(a) : "l"(p));
    return a;
}
__device__ __forceinline__ void ldsm4(uint32_t addr, uint32_t& r0, uint32_t& r1, uint32_t& r2, uint32_t& r3) {
    asm volatile("ldmatrix.sync.aligned.m8n8.x4.shared.b16 {%0,%1,%2,%3}, [%4];"
                 : "=r"(r0), "=r"(r1), "=r"(r2), "=r"(r3) : "r"(addr));
}
__device__ __forceinline__ void ldsm4t(uint32_t addr, uint32_t& r0, uint32_t& r1, uint32_t& r2, uint32_t& r3) {
    asm volatile("ldmatrix.sync.aligned.m8n8.x4.trans.shared.b16 {%0,%1,%2,%3}, [%4];"
                 : "=r"(r0), "=r"(r1), "=r"(r2), "=r"(r3) : "r"(addr));
}
__device__ __forceinline__ void mma_bf16(float c[4], const uint32_t a[4], uint32_t b0, uint32_t b1) {
    asm volatile(
        "mma.sync.aligned.m16n8k16.row.col.f32.bf16.bf16.f32 "
        "{%0,%1,%2,%3}, {%4,%5,%6,%7}, {%8,%9}, {%0,%1,%2,%3};"
        : "+f"(c[0]), "+f"(c[1]), "+f"(c[2]), "+f"(c[3])
        : "r"(a[0]), "r"(a[1]), "r"(a[2]), "r"(a[3]), "r"(b0), "r"(b1));
}
__device__ __forceinline__ void splitf2(float x, float y, uint32_t& h, uint32_t& l) {
    __nv_bfloat162 hh = __float22bfloat162_rn(make_float2(x, y));
    float2 hf = __bfloat1622float2(hh);
    __nv_bfloat162 ll = __float22bfloat162_rn(make_float2(x - hf.x, y - hf.y));
    h = *(uint32_t*)&hh; l = *(uint32_t*)&ll;
}
__device__ __forceinline__ void split2(float4 v, uint2& hi, uint2& lo) {
    uint32_t h0, l0, h1, l1;
    splitf2(v.x, v.y, h0, l0);
    splitf2(v.z, v.w, h1, l1);
    hi = make_uint2(h0, h1);
    lo = make_uint2(l0, l1);
}
#define CP_ASYNC16(dst, src) asm volatile("cp.async.cg.shared.global [%0], [%1], 16;" :: "r"(dst), "l"(src) : "memory")
#define CP_COMMIT()          asm volatile("cp.async.commit_group;" ::: "memory")
#define CP_WAIT0()           asm volatile("cp.async.wait_group 0;" ::: "memory")
#define CP_WAIT1()           asm volatile("cp.async.wait_group 1;" ::: "memory")

// -------------------- multi-source fp32 -> bf16 hi/lo split --------------------
#define NJOBS 7
struct SplitJobs {
    const float* src[NJOBS];
    bf16* dh[NJOBS];
    bf16* dl[NJOBS];
    int n[NJOBS];
    int start[NJOBS + 1];
};
__global__ __launch_bounds__(256) void multi_split(SplitJobs J)
{
    int b = blockIdx.x;
    int j = 0;
    #pragma unroll
    for (int t = 0; t < NJOBS - 1; t++)
        if (b >= J.start[t + 1]) j = t + 1;
    int local = b - J.start[j];
    int i = (local * 256 + threadIdx.x) * 4;
    if (i < J.n[j]) {
        float4 v = *(const float4*)(J.src[j] + i);
        uint2 h, l; split2(v, h, l);
        *(uint2*)(J.dh[j] + i) = h;
        *(uint2*)(J.dl[j] + i) = l;
    }
}

// -------------------- fold 3-tap conv into weight columns (2 jobs via grid.z) ----
__global__ __launch_bounds__(128) void fold_split2(
    bf16* __restrict__ H0, bf16* __restrict__ L0, const float* __restrict__ W0, const float* __restrict__ w0c,
    bf16* __restrict__ H1, bf16* __restrict__ L1, const float* __restrict__ W1p, const float* __restrict__ w1c)
{
    __shared__ float rb[D];
    const int row = blockIdx.x, t = threadIdx.x;
    const float* W = blockIdx.z ? W1p : W0;
    const float* w = blockIdx.z ? w1c : w0c;
    bf16* H = blockIdx.z ? H1 : H0;
    bf16* L = blockIdx.z ? L1 : L0;
    float4 v = *(const float4*)(W + (size_t)row * D + t * 4);
    *(float4*)&rb[t * 4] = v;
    __syncthreads();
    const float w0 = w[0], w1 = w[1], w2 = w[2];
    float y[4];
    #pragma unroll
    for (int i = 0; i < 4; i++) {
        int c = t * 4 + i;
        float xm = (c > 0) ? rb[c - 1] : 0.f;
        float xp = (c < D - 1) ? rb[c + 1] : 0.f;
        y[i] = w2 * xm + w1 * rb[c] + w0 * xp;
    }
    uint32_t h0, l0, h1, l1;
    splitf2(y[0], y[1], h0, l0);
    splitf2(y[2], y[3], h1, l1);
    *(uint2*)(H + (size_t)row * D + t * 4) = make_uint2(h0, h1);
    *(uint2*)(L + (size_t)row * D + t * 4) = make_uint2(l0, l1);
}

// ==================== single-stage streamed split-bf16 mma GEMM, 2 CTAs/SM ========
#define T_AH 0
#define T_AL 18432
#define T_BH 36864
#define T_BL 55296
#define TCG_SMEM 73728

__global__ __launch_bounds__(256, 2) void mma_gemm(
    float* __restrict__ C, bf16* __restrict__ Ch, bf16* __restrict__ Cl,
    const bf16* __restrict__ Ah, const bf16* __restrict__ Al,
    const bf16* __restrict__ Bh, const bf16* __restrict__ Bl,
    int M, int Nt, int K, const float* __restrict__ bias, int act, int mode)
{
    extern __shared__ char smem[];
    const uint32_t sb = smem_u32(smem);
    const int tid = threadIdx.x, wid = tid >> 5, lane = tid & 31;
    const int m0 = blockIdx.y * 128, n0 = blockIdx.x * 128;
    const int wm = (wid & 3) << 5;
    const int wn = (wid >> 2) << 6;
    const int quad = lane >> 3, r = lane & 7;
    const int arow = ((quad & 1) << 3) + r, ak = (quad >> 1) << 3;
    const int brow = ((quad >> 1) << 3) + r, bk = (quad & 1) << 3;

    float acc[2][8][4];
    #pragma unroll
    for (int i = 0; i < 2; i++)
        #pragma unroll
        for (int j = 0; j < 8; j++)
            #pragma unroll
            for (int q = 0; q < 4; q++) acc[i][j][q] = 0.f;

    const int nit = K >> 6;

    #pragma unroll
    for (int j = 0; j < 4; j++) {
        int ch = tid + (j << 8);
        int row = ch >> 3, cc = ch & 7;
        uint32_t so = row * 144 + cc * 16;
        size_t ga = (size_t)(m0 + row) * K + cc * 8;
        size_t gb = (size_t)(n0 + row) * K + cc * 8;
        CP_ASYNC16(sb + T_AH + so, Ah + ga);
        CP_ASYNC16(sb + T_AL + so, Al + ga);
        CP_ASYNC16(sb + T_BH + so, Bh + gb);
        CP_ASYNC16(sb + T_BL + so, Bl + gb);
    }
    CP_COMMIT();

    for (int it = 0; it < nit; it++) {
        CP_WAIT0();
        __syncthreads();
        #pragma unroll
        for (int kc = 0; kc < 4; kc++) {
            uint32_t ah[2][4], al[2][4];
            #pragma unroll
            for (int i = 0; i < 2; i++) {
                uint32_t ao = sb + (wm + (i << 4) + arow) * 144 + ((kc << 4) + ak) * 2;
                ldsm4(ao + T_AH, ah[i][0], ah[i][1], ah[i][2], ah[i][3]);
                ldsm4(ao + T_AL, al[i][0], al[i][1], al[i][2], al[i][3]);
            }
            #pragma unroll
            for (int jj = 0; jj < 4; jj++) {
                uint32_t bo = sb + (wn + (jj << 4) + brow) * 144 + ((kc << 4) + bk) * 2;
                uint32_t bh0, bh1, bh2, bh3, bl0, bl1, bl2, bl3;
                ldsm4(bo + T_BH, bh0, bh1, bh2, bh3);
                ldsm4(bo + T_BL, bl0, bl1, bl2, bl3);
                #pragma unroll
                for (int i = 0; i < 2; i++) {
                    mma_bf16(acc[i][2 * jj],     ah[i], bh0, bh1);
                    mma_bf16(acc[i][2 * jj],     ah[i], bl0, bl1);
                    mma_bf16(acc[i][2 * jj],     al[i], bh0, bh1);
                    mma_bf16(acc[i][2 * jj + 1], ah[i], bh2, bh3);
                    mma_bf16(acc[i][2 * jj + 1], ah[i], bl2, bl3);
                    mma_bf16(acc[i][2 * jj + 1], al[i], bh2, bh3);
                }
            }
        }
        __syncthreads();
        if (it + 1 < nit) {
            const int k0 = (it + 1) << 6;
            #pragma unroll
            for (int j = 0; j < 4; j++) {
                int ch = tid + (j << 8);
                int row = ch >> 3, cc = ch & 7;
                uint32_t so = row * 144 + cc * 16;
                size_t ga = (size_t)(m0 + row) * K + k0 + cc * 8;
                size_t gb = (size_t)(n0 + row) * K + k0 + cc * 8;
                CP_ASYNC16(sb + T_AH + so, Ah + ga);
                CP_ASYNC16(sb + T_AL + so, Al + ga);
                CP_ASYNC16(sb + T_BH + so, Bh + gb);
                CP_ASYNC16(sb + T_BL + so, Bl + gb);
            }
            CP_COMMIT();
        }
    }

    const int g = lane >> 2, tg = (lane & 3) << 1;
    #pragma unroll
    for (int i = 0; i < 2; i++) {
        const int row0 = m0 + wm + (i << 4) + g;
        #pragma unroll
        for (int j = 0; j < 8; j++) {
            const int col = n0 + wn + (j << 3) + tg;
            float v0 = acc[i][j][0], v1 = acc[i][j][1];
            float v2 = acc[i][j][2], v3 = acc[i][j][3];
            if (mode == 1) {
                if (col < KVD) {
                    uint32_t h0, l0, h1, l1;
                    splitf2(v0, v1, h0, l0);
                    splitf2(v2, v3, h1, l1);
                    *(uint32_t*)(Ch + (size_t)row0 * KVD + col) = h0;
                    *(uint32_t*)(Ch + (size_t)(row0 + 8) * KVD + col) = h1;
                    *(uint32_t*)(Cl + (size_t)row0 * KVD + col) = l0;
                    *(uint32_t*)(Cl + (size_t)(row0 + 8) * KVD + col) = l1;
                } else {
                    *(float2*)(C + (size_t)row0 * D + col - KVD) = make_float2(v0, v1);
                    *(float2*)(C + (size_t)(row0 + 8) * D + col - KVD) = make_float2(v2, v3);
                }
                continue;
            }
            float b0 = 0.f, b1 = 0.f;
            if (bias) { b0 = bias[col]; b1 = bias[col + 1]; }
            v0 += b0; v1 += b1; v2 += b0; v3 += b1;
            if (act) {
                v0 = 0.5f * v0 * (1.0f + erff(v0 * 0.70710678118654752f));
                v1 = 0.5f * v1 * (1.0f + erff(v1 * 0.70710678118654752f));
                v2 = 0.5f * v2 * (1.0f + erff(v2 * 0.70710678118654752f));
                v3 = 0.5f * v3 * (1.0f + erff(v3 * 0.70710678118654752f));
            }
            if (C) {
                *(float2*)(C + (size_t)row0 * Nt + col) = make_float2(v0, v1);
                *(float2*)(C + (size_t)(row0 + 8) * Nt + col) = make_float2(v2, v3);
            }
            if (Ch) {
                uint32_t h0, l0, h1, l1;
                splitf2(v0, v1, h0, l0);
                splitf2(v2, v3, h1, l1);
                *(uint32_t*)(Ch + (size_t)row0 * Nt + col) = h0;
                *(uint32_t*)(Ch + (size_t)(row0 + 8) * Nt + col) = h1;
                if (Cl) {
                    *(uint32_t*)(Cl + (size_t)row0 * Nt + col) = l0;
                    *(uint32_t*)(Cl + (size_t)(row0 + 8) * Nt + col) = l1;
                }
            }
        }
    }
}

// -------------------- GEMM NN (fp32, weight folding; grid.z selects job) ----------
__global__ __launch_bounds__(256) void gemm_nn2(
    float* __restrict__ C0, const float* __restrict__ A0, const float* __restrict__ B0p,
    float* __restrict__ C1, const float* __restrict__ A1, const float* __restrict__ B1p,
    int M, int N, int K)
{
    float* C = blockIdx.z ? C1 : C0;
    const float* A = blockIdx.z ? A1 : A0;
    const float* B = blockIdx.z ? B1p : B0p;
    __shared__ float As[16][64];
    __shared__ float Bs[16][64];
    const int tid = threadIdx.x;
    const int tx = tid & 15, ty = tid >> 4;
    const int lr = tid >> 2, lc = (tid & 3) << 2;
    const int bkr = tid >> 4, bnc = (tid & 15) << 2;
    const float* Ab = A + (size_t)blockIdx.y * 64 * K;
    float acc[4][4] = {};
    for (int k0 = 0; k0 < K; k0 += 16) {
        float4 a4 = *(const float4*)(Ab + (size_t)lr * K + k0 + lc);
        float4 b4 = *(const float4*)(B + (size_t)(k0 + bkr) * N + blockIdx.x * 64 + bnc);
        __syncthreads();
        As[lc + 0][lr] = a4.x; As[lc + 1][lr] = a4.y; As[lc + 2][lr] = a4.z; As[lc + 3][lr] = a4.w;
        *(float4*)&Bs[bkr][bnc] = b4;
        __syncthreads();
        #pragma unroll
        for (int k = 0; k < 16; k++) {
            float4 av = *(const float4*)&As[k][ty << 2];
            float4 bv = *(const float4*)&Bs[k][tx << 2];
            float a[4] = {av.x, av.y, av.z, av.w};
            float b[4] = {bv.x, bv.y, bv.z, bv.w};
            #pragma unroll
            for (int i = 0; i < 4; i++)
                #pragma unroll
                for (int j = 0; j < 4; j++) acc[i][j] += a[i] * b[j];
        }
    }
    #pragma unroll
    for (int i = 0; i < 4; i++) {
        int m = blockIdx.y * 64 + (ty << 2) + i;
        #pragma unroll
        for (int j = 0; j < 4; j++)
            C[(size_t)m * N + blockIdx.x * 64 + (tx << 2) + j] = acc[i][j];
    }
}

// ==================== tensor-core flash attention (2 CTAs/SM) ====================
#define AQ_H 0
#define AQ_L 18432
#define AK_B(s) (36864 + (s) * 18432)
#define AV_B(s) (73728 + (s) * 9216)
#define AT_SMEM 92160

__global__ __launch_bounds__(256, 2) void attn_mma(
    bf16* __restrict__ Oh, bf16* __restrict__ Ol,
    const bf16* __restrict__ Qh, const bf16* __restrict__ Ql,
    const bf16* __restrict__ Kh, const bf16* __restrict__ Kl,
    const bf16* __restrict__ Vb)
{
    extern __shared__ char smem[];
    const uint32_t sb = smem_u32(smem);
    const int tid = threadIdx.x, wid = tid >> 5, lane = tid & 31;
    const int b = blockIdx.z, h = blockIdx.y;
    const int q0 = blockIdx.x * 128;
    const size_t tok0 = (size_t)b * SEQL;
    const int hc = h * 64;
    const int quad = lane >> 3, r = lane & 7;
    const int arow = ((quad & 1) << 3) + r, ak = (quad >> 1) << 3;
    const int brow = ((quad >> 1) << 3) + r, bk = (quad & 1) << 3;
    const int vrow = (((lane >> 3) & 1) << 3) + (lane & 7);
    const int vch = (lane >> 4) << 3;
    const int g = lane >> 2, tg = lane & 3;
    const int wq0 = wid << 4;

    {
        #pragma unroll
        for (int j = 0; j < 4; j++) {
            int ch = tid + (j << 8);
            int row = ch >> 3, cc = ch & 7;
            uint32_t so = row * 144 + cc * 16;
            size_t ga = (tok0 + q0 + row) * D + hc + cc * 8;
            CP_ASYNC16(sb + AQ_H + so, Qh + ga);
            CP_ASYNC16(sb + AQ_L + so, Ql + ga);
        }
        #pragma unroll
        for (int j = 0; j < 2; j++) {
            int ch = tid + (j << 8);
            int row = ch >> 3, cc = ch & 7;
            uint32_t so = row * 144 + cc * 16;
            size_t ga = (tok0 + row) * KVD + hc + cc * 8;
            CP_ASYNC16(sb + AK_B(0) + so, Kh + ga);
            CP_ASYNC16(sb + AK_B(0) + 9216 + so, Kl + ga);
            CP_ASYNC16(sb + AV_B(0) + so, Vb + ga);
        }
        CP_COMMIT();
    }

    float o[8][4];
    #pragma unroll
    for (int j = 0; j < 8; j++)
        #pragma unroll
        for (int q = 0; q < 4; q++) o[j][q] = 0.f;
    float m0r = -1e30f, m1r = -1e30f, l0r = 0.f, l1r = 0.f;

    for (int kt = 0; kt < SEQL / 64; kt++) {
        const int s = kt & 1;
        if (kt + 1 < SEQL / 64) {
            const size_t kb = tok0 + (size_t)(kt + 1) * 64;
            #pragma unroll
            for (int j = 0; j < 2; j++) {
                int ch = tid + (j << 8);
                int row = ch >> 3, cc = ch & 7;
                uint32_t so = row * 144 + cc * 16;
                size_t ga = (kb + row) * KVD + hc + cc * 8;
                CP_ASYNC16(sb + AK_B(1 - s) + so, Kh + ga);
                CP_ASYNC16(sb + AK_B(1 - s) + 9216 + so, Kl + ga);
                CP_ASYNC16(sb + AV_B(1 - s) + so, Vb + ga);
            }
            CP_COMMIT();
            CP_WAIT1();
        } else {
            CP_WAIT0();
        }
        __syncthreads();

        float sc[8][4];
        #pragma unroll
        for (int j = 0; j < 8; j++)
            #pragma unroll
            for (int q = 0; q < 4; q++) sc[j][q] = 0.f;
        #pragma unroll
        for (int kc = 0; kc < 4; kc++) {
            uint32_t ah[4], al[4];
            uint32_t ao = sb + (wq0 + arow) * 144 + ((kc << 4) + ak) * 2;
            ldsm4(ao + AQ_H, ah[0], ah[1], ah[2], ah[3]);
            ldsm4(ao + AQ_L, al[0], al[1], al[2], al[3]);
            #pragma unroll
            for (int jj = 0; jj < 4; jj++) {
                uint32_t bo = sb + AK_B(s) + ((jj << 4) + brow) * 144 + ((kc << 4) + bk) * 2;
                uint32_t bh0, bh1, bh2, bh3, bl0, bl1, bl2, bl3;
                ldsm4(bo, bh0, bh1, bh2, bh3);
                ldsm4(bo + 9216, bl0, bl1, bl2, bl3);
                mma_bf16(sc[2 * jj],     ah, bh0, bh1);
                mma_bf16(sc[2 * jj],     ah, bl0, bl1);
                mma_bf16(sc[2 * jj],     al, bh0, bh1);
                mma_bf16(sc[2 * jj + 1], ah, bh2, bh3);
                mma_bf16(sc[2 * jj + 1], ah, bl2, bl3);
                mma_bf16(sc[2 * jj + 1], al, bh2, bh3);
            }
        }
        float mx0 = -1e30f, mx1 = -1e30f;
        #pragma unroll
        for (int j = 0; j < 8; j++) {
            sc[j][0] *= ATT_SCALE; sc[j][1] *= ATT_SCALE;
            sc[j][2] *= ATT_SCALE; sc[j][3] *= ATT_SCALE;
            mx0 = fmaxf(mx0, fmaxf(sc[j][0], sc[j][1]));
            mx1 = fmaxf(mx1, fmaxf(sc[j][2], sc[j][3]));
        }
        mx0 = fmaxf(mx0, __shfl_xor_sync(0xffffffffu, mx0, 1));
        mx0 = fmaxf(mx0, __shfl_xor_sync(0xffffffffu, mx0, 2));
        mx1 = fmaxf(mx1, __shfl_xor_sync(0xffffffffu, mx1, 1));
        mx1 = fmaxf(mx1, __shfl_xor_sync(0xffffffffu, mx1, 2));
        float mn0 = fmaxf(m0r, mx0), mn1 = fmaxf(m1r, mx1);
        float a0 = __expf(m0r - mn0), a1 = __expf(m1r - mn1);
        m0r = mn0; m1r = mn1;
        float rs0 = 0.f, rs1 = 0.f;
        #pragma unroll
        for (int j = 0; j < 8; j++) {
            sc[j][0] = __expf(sc[j][0] - mn0); sc[j][1] = __expf(sc[j][1] - mn0);
            sc[j][2] = __expf(sc[j][2] - mn1); sc[j][3] = __expf(sc[j][3] - mn1);
            rs0 += sc[j][0] + sc[j][1];
            rs1 += sc[j][2] + sc[j][3];
        }
        rs0 += __shfl_xor_sync(0xffffffffu, rs0, 1);
        rs0 += __shfl_xor_sync(0xffffffffu, rs0, 2);
        rs1 += __shfl_xor_sync(0xffffffffu, rs1, 1);
        rs1 += __shfl_xor_sync(0xffffffffu, rs1, 2);
        l0r = l0r * a0 + rs0;
        l1r = l1r * a1 + rs1;
        #pragma unroll
        for (int j = 0; j < 8; j++) {
            o[j][0] *= a0; o[j][1] *= a0; o[j][2] *= a1; o[j][3] *= a1;
        }
        #pragma unroll
        for (int kk = 0; kk < 4; kk++) {
            uint32_t pa[4];
            __nv_bfloat162 t0 = __float22bfloat162_rn(make_float2(sc[2 * kk][0], sc[2 * kk][1]));
            __nv_bfloat162 t1 = __float22bfloat162_rn(make_float2(sc[2 * kk][2], sc[2 * kk][3]));
            __nv_bfloat162 t2 = __float22bfloat162_rn(make_float2(sc[2 * kk + 1][0], sc[2 * kk + 1][1]));
            __nv_bfloat162 t3 = __float22bfloat162_rn(make_float2(sc[2 * kk + 1][2], sc[2 * kk + 1][3]));
            pa[0] = *(uint32_t*)&t0; pa[1] = *(uint32_t*)&t1;
            pa[2] = *(uint32_t*)&t2; pa[3] = *(uint32_t*)&t3;
            #pragma unroll
            for (int jj = 0; jj < 4; jj++) {
                uint32_t bo = sb + AV_B(s) + ((kk << 4) + vrow) * 144 + ((jj << 4) + vch) * 2;
                uint32_t b0, b1, b2, b3;
                ldsm4t(bo, b0, b1, b2, b3);
                mma_bf16(o[2 * jj],     pa, b0, b1);
                mma_bf16(o[2 * jj + 1], pa, b2, b3);
            }
        }
        __syncthreads();
    }
    const float inv0 = 1.0f / l0r, inv1 = 1.0f / l1r;
    #pragma unroll
    for (int j = 0; j < 8; j++) {
        int col = hc + (j << 3) + (tg << 1);
        size_t r0 = (tok0 + q0 + wq0 + g) * D + col;
        size_t r1 = (tok0 + q0 + wq0 + g + 8) * D + col;
        uint32_t h0, l0, h1, l1;
        splitf2(o[j][0] * inv0, o[j][1] * inv0, h0, l0);
        splitf2(o[j][2] * inv1, o[j][3] * inv1, h1, l1);
        *(uint32_t*)(Oh + r0) = h0; *(uint32_t*)(Ol + r0) = l0;
        *(uint32_t*)(Oh + r1) = h1; *(uint32_t*)(Ol + r1) = l1;
    }
}

// -------------------- LN: 2 rows per 256-thread block --------------------
__global__ __launch_bounds__(256) void ln_kernel(
    float* __restrict__ out, bf16* __restrict__ outH, bf16* __restrict__ outL,
    const float* __restrict__ a, const float* __restrict__ b,
    const bf16* __restrict__ bH, const bf16* __restrict__ bL,
    const float* __restrict__ g, const float* __restrict__ be,
    float* __restrict__ hn_out, int do_hn)
{
    __shared__ float sh[2][8];
    const int half = threadIdx.x >> 7;
    const int t = threadIdx.x & 127;
    const int row = blockIdx.x * 2 + half;
    float4 av = *(const float4*)(a + (size_t)row * D + t * 4);
    float bvv[4];
    if (b) {
        float4 bv = *(const float4*)(b + (size_t)row * D + t * 4);
        bvv[0] = bv.x; bvv[1] = bv.y; bvv[2] = bv.z; bvv[3] = bv.w;
    } else {
        uint2 hv = *(const uint2*)(bH + (size_t)row * D + t * 4);
        uint2 lv = *(const uint2*)(bL + (size_t)row * D + t * 4);
        float2 h0 = __bfloat1622float2(*(__nv_bfloat162*)&hv.x);
        float2 h1 = __bfloat1622float2(*(__nv_bfloat162*)&hv.y);
        float2 l0 = __bfloat1622float2(*(__nv_bfloat162*)&lv.x);
        float2 l1 = __bfloat1622float2(*(__nv_bfloat162*)&lv.y);
        bvv[0] = h0.x + l0.x; bvv[1] = h0.y + l0.y;
        bvv[2] = h1.x + l1.x; bvv[3] = h1.y + l1.y;
    }
    float v[4] = {av.x + bvv[0], av.y + bvv[1], av.z + bvv[2], av.w + bvv[3]};
    float s = v[0] + v[1] + v[2] + v[3];
    float s2 = v[0] * v[0] + v[1] * v[1] + v[2] * v[2] + v[3] * v[3];
    #pragma unroll
    for (int off = 16; off; off >>= 1) {
        s += __shfl_xor_sync(0xffffffffu, s, off);
        s2 += __shfl_xor_sync(0xffffffffu, s2, off);
    }
    if ((t & 31) == 0) { sh[half][t >> 5] = s; sh[half][4 + (t >> 5)] = s2; }
    __syncthreads();
    s = sh[half][0] + sh[half][1] + sh[half][2] + sh[half][3];
    s2 = sh[half][4] + sh[half][5] + sh[half][6] + sh[half][7];
    const float mean = s * (1.0f / D);
    const float rstd = rsqrtf(s2 * (1.0f / D) - mean * mean + 1e-5f);
    float4 gv = *(const float4*)(g + t * 4);
    float4 bev = *(const float4*)(be + t * 4);
    float y[4];
    y[0] = (v[0] - mean) * rstd * gv.x + bev.x;
    y[1] = (v[1] - mean) * rstd * gv.y + bev.y;
    y[2] = (v[2] - mean) * rstd * gv.z + bev.z;
    y[3] = (v[3] - mean) * rstd * gv.w + bev.w;
    if (out)
        *(float4*)(out + (size_t)row * D + t * 4) = make_float4(y[0], y[1], y[2], y[3]);
    if (outH) {
        uint32_t h0, l0, h1, l1;
        splitf2(y[0], y[1], h0, l0);
        splitf2(y[2], y[3], h1, l1);
        *(uint2*)(outH + (size_t)row * D + t * 4) = make_uint2(h0, h1);
        *(uint2*)(outL + (size_t)row * D + t * 4) = make_uint2(l0, l1);
    }
    if (do_hn && (row & (SEQL - 1)) == SEQL - 1)
        *(float4*)(hn_out + (size_t)(row >> 10) * D + t * 4) = av;
}

// -------------------- launch --------------------
extern "C" void kernel_launch(void* const* d_in, const int* in_sizes, int n_in,
                              void* d_out, int out_size)
{
    const float* input   = (const float*)d_in[0];
    const float* wq_c    = (const float*)d_in[3];
    const float* fc_c    = (const float*)d_in[5];
    const float* wq_g    = (const float*)d_in[6];
    const float* wk_g    = (const float*)d_in[7];
    const float* fc_g    = (const float*)d_in[8];
    const float* wq_x    = (const float*)d_in[9];
    const float* fc_x    = (const float*)d_in[11];
    const float* conv1_w = (const float*)d_in[12];
    const float* conv2_w = (const float*)d_in[13];
    const float* ln1_g = (const float*)d_in[14];
    const float* ln1_b = (const float*)d_in[15];
    const float* ln2_g = (const float*)d_in[16];
    const float* ln2_b = (const float*)d_in[17];
    const float* ln3_g = (const float*)d_in[18];
    const float* ln3_b = (const float*)d_in[19];
    const float* ln4_g = (const float*)d_in[20];
    const float* ln4_b = (const float*)d_in[21];
    const float* mlp_w1 = (const float*)d_in[22];
    const float* mlp_b1 = (const float*)d_in[23];
    const float* mlp_w2 = (const float*)d_in[24];
    const float* mlp_b2 = (const float*)d_in[25];

    float *M1, *M3, *B0, *B1;
    bf16 *Wh, *Wl, *XH, *XL, *KVH, *KVL, *QH, *QL;
    bf16 *ATH, *ATL, *X1H, *X1L, *X2H, *X2L, *X3H, *X3L, *HIDH, *HIDL;
    cudaGetSymbolAddress((void**)&M1, d_M1);
    cudaGetSymbolAddress((void**)&M3, d_M3);
    cudaGetSymbolAddress((void**)&B0, d_B0);
    cudaGetSymbolAddress((void**)&B1, d_B1);
    cudaGetSymbolAddress((void**)&Wh, d_Wh);
    cudaGetSymbolAddress((void**)&Wl, d_Wl);
    cudaGetSymbolAddress((void**)&XH, d_XH);
    cudaGetSymbolAddress((void**)&XL, d_XL);
    cudaGetSymbolAddress((void**)&KVH, d_KVH);
    cudaGetSymbolAddress((void**)&KVL, d_KVL);
    cudaGetSymbolAddress((void**)&QH, d_QH);
    cudaGetSymbolAddress((void**)&QL, d_QL);
    cudaGetSymbolAddress((void**)&ATH, d_ATH);
    cudaGetSymbolAddress((void**)&ATL, d_ATL);
    cudaGetSymbolAddress((void**)&X1H, d_X1H);
    cudaGetSymbolAddress((void**)&X1L, d_X1L);
    cudaGetSymbolAddress((void**)&X2H, d_X2H);
    cudaGetSymbolAddress((void**)&X2L, d_X2L);
    cudaGetSymbolAddress((void**)&X3H, d_X3H);
    cudaGetSymbolAddress((void**)&X3L, d_X3L);
    cudaGetSymbolAddress((void**)&HIDH, d_HIDH);
    cudaGetSymbolAddress((void**)&HIDL, d_HIDL);

    cudaFuncSetAttribute(mma_gemm, cudaFuncAttributeMaxDynamicSharedMemorySize, TCG_SMEM);
    cudaFuncSetAttribute(attn_mma, cudaFuncAttributeMaxDynamicSharedMemorySize, AT_SMEM);

    float* outp = (float*)d_out;
    const size_t out_main = (size_t)N_TOK * D;
    float* hnp = outp + out_main;
    int do_hn = (out_size >= (int)(out_main + BSZ * D)) ? 1 : 0;
    if (!do_hn) hnp = outp;

    const dim3 blk(256);
    const dim3 tg512(D / 128, N_TOK / 128);
    const dim3 tg1536(12, N_TOK / 128);
    const dim3 tg2048(DFF / 128, N_TOK / 128);
    const int LN_G = N_TOK / 2;

    // ---- prep phase: 3 launches ----
    gemm_nn2<<<dim3(D / 64, D / 64, 2), blk>>>(M1, fc_c, wq_c, M3, fc_x, wq_x, D, D, D);
    {
        SplitJobs J;
        const float* srcs[NJOBS] = {wk_g, wq_g, fc_g, M3, mlp_w1, mlp_w2, input};
        bf16* dhs[NJOBS] = {Wh + OFF_WKG, Wh + OFF_WQG, Wh + OFF_FCG, Wh + OFF_M3,
                            Wh + OFF_W1, Wh + OFF_W2, XH};
        bf16* dls[NJOBS] = {Wl + OFF_WKG, Wl + OFF_WQG, Wl + OFF_FCG, Wl + OFF_M3,
                            Wl + OFF_W1, Wl + OFF_W2, XL};
        int ns[NJOBS] = {D * D, D * D, D * D, D * D, D * DFF, D * DFF, N_TOK * D};
        int total = 0;
        for (int j = 0; j < NJOBS; j++) {
            J.src[j] = srcs[j]; J.dh[j] = dhs[j]; J.dl[j] = dls[j]; J.n[j] = ns[j];
            J.start[j] = total;
            total += (ns[j] + 1023) / 1024;
        }
        J.start[NJOBS] = total;
        multi_split<<<total, blk>>>(J);
    }
    fold_split2<<<dim3(D, 1, 2), 128>>>(Wh + OFF_M1, Wl + OFF_M1, M1, conv1_w,
                                        Wh + OFF_WQG2, Wl + OFF_WQG2, wq_g, conv2_w);

    // ---- merged: KV = X@[wkg;wqg]^T (split), u = X@M1c^T (fp32 B1)
    mma_gemm<<<tg1536, blk, TCG_SMEM>>>(B1, KVH, KVL, XH, XL,
                                        Wh + OFF_WKG, Wl + OFF_WKG, N_TOK, 1536, D, nullptr, 0, 1);

    // ---- x1 = LN1(u + input)
    ln_kernel<<<LN_G, 256>>>(nullptr, X1H, X1L, B1, input, nullptr, nullptr, ln1_g, ln1_b, hnp, 0);

    // ---- Q; attention; g; x2 = LN2(g + x1)
    mma_gemm<<<tg512, blk, TCG_SMEM>>>(nullptr, QH, QL, X1H, X1L,
                                       Wh + OFF_WQG2, Wl + OFF_WQG2, N_TOK, D, D, nullptr, 0, 0);
    attn_mma<<<dim3(SEQL / 128, 8, BSZ), blk, AT_SMEM>>>(ATH, ATL, QH, QL, KVH, KVL, KVH + 512);
    mma_gemm<<<tg512, blk, TCG_SMEM>>>(B0, nullptr, nullptr, ATH, ATL,
                                       Wh + OFF_FCG, Wl + OFF_FCG, N_TOK, D, D, nullptr, 0, 0);
    ln_kernel<<<LN_G, 256>>>(nullptr, X2H, X2L, B0, nullptr, X1H, X1L, ln2_g, ln2_b, hnp, 0);

    // ---- h = x2 @ M3^T; x3 = LN3(h + x2); hn
    mma_gemm<<<tg512, blk, TCG_SMEM>>>(B1, nullptr, nullptr, X2H, X2L,
                                       Wh + OFF_M3, Wl + OFF_M3, N_TOK, D, D, nullptr, 0, 0);
    ln_kernel<<<LN_G, 256>>>(nullptr, X3H, X3L, B1, nullptr, X2H, X2L, ln3_g, ln3_b, hnp, do_hn);

    // ---- MLP
    mma_gemm<<<tg2048, blk, TCG_SMEM>>>(nullptr, HIDH, HIDL, X3H, X3L,
                                        Wh + OFF_W1, Wl + OFF_W1, N_TOK, DFF, D, mlp_b1, 1, 0);
    mma_gemm<<<tg512, blk, TCG_SMEM>>>(B0, nullptr, nullptr, HIDH, HIDL,
                                       Wh + OFF_W2, Wl + OFF_W2, N_TOK, D, DFF, mlp_b2, 0, 0);
    ln_kernel<<<LN_G, 256>>>(outp, nullptr, nullptr, B0, nullptr, X3H, X3L, ln4_g, ln4_b, hnp, 0);
}